// round 4
// baseline (speedup 1.0000x reference)
#include <cuda_runtime.h>
#include <math.h>

#define T_DIM 2048
#define D_DIM 1024
#define B_DIM 2
#define H_NUM 16
#define M_ROWS 4096   // B*T

typedef unsigned long long ull;

// ---- packed f32x2 helpers (Blackwell FFMA2: only reachable via PTX) ----
__device__ __forceinline__ ull pack2(float lo, float hi) {
    ull r; asm("mov.b64 %0, {%1, %2};" : "=l"(r) : "f"(lo), "f"(hi)); return r;
}
__device__ __forceinline__ float2 unpk2(ull v) {
    float2 f; asm("mov.b64 {%0, %1}, %2;" : "=f"(f.x), "=f"(f.y) : "l"(v)); return f;
}
#define FMA2(d, a, b) asm("fma.rn.f32x2 %0, %1, %2, %0;" : "+l"(d) : "l"(a), "l"(b))
#define MUL2(d, a)    asm("mul.rn.f32x2 %0, %0, %1;"     : "+l"(d) : "l"(a))
__device__ __forceinline__ ull d2l(double d) { return __double_as_longlong(d); }

// ---------------- scratch (device globals; no allocation) ----------------
__device__ float g_y [(size_t)M_ROWS * D_DIM];
__device__ float g_q [(size_t)M_ROWS * D_DIM];
__device__ float g_kk[(size_t)M_ROWS * D_DIM];
__device__ float g_v [(size_t)M_ROWS * D_DIM];
__device__ float g_o [(size_t)M_ROWS * D_DIM];
__device__ float g_x1[(size_t)M_ROWS * D_DIM];
__device__ float g_h [(size_t)M_ROWS * 4 * D_DIM];
__device__ float g_gl[(size_t)M_ROWS * 2 * D_DIM];
__device__ float g_ta[(size_t)M_ROWS * 8];

// ---------------- RMSNorm ----------------
__global__ void rmsnorm_k(const float* __restrict__ X, const float* __restrict__ W,
                          float* __restrict__ Y) {
    int row = blockIdx.x;
    const float4* x4 = (const float4*)(X + (size_t)row * D_DIM);
    float4 v = x4[threadIdx.x];
    float ss = v.x*v.x + v.y*v.y + v.z*v.z + v.w*v.w;
    #pragma unroll
    for (int off = 16; off; off >>= 1) ss += __shfl_xor_sync(0xffffffffu, ss, off);
    __shared__ float sred[8];
    if ((threadIdx.x & 31) == 0) sred[threadIdx.x >> 5] = ss;
    __syncthreads();
    float tot = 0.f;
    #pragma unroll
    for (int i = 0; i < 8; i++) tot += sred[i];
    float inv = rsqrtf(tot * (1.0f / D_DIM) + 1e-6f);
    float4 w = ((const float4*)W)[threadIdx.x];
    float4 o;
    o.x = v.x * inv * w.x; o.y = v.y * inv * w.y;
    o.z = v.z * inv * w.z; o.w = v.w * inv * w.w;
    ((float4*)(Y + (size_t)row * D_DIM))[threadIdx.x] = o;
}

// ---------------- LoRA A: T[m,r] = sum_k Y[m,k]*A[r,k] ----------------
__global__ void lora_a_k(const float* __restrict__ Y, const float* __restrict__ A,
                         float* __restrict__ Tout, int K) {
    int row  = blockIdx.x * 8 + (threadIdx.x >> 5);
    int lane = threadIdx.x & 31;
    const float* y = Y + (size_t)row * K;
    float acc[8] = {0,0,0,0,0,0,0,0};
    for (int k = lane; k < K; k += 32) {
        float yv = y[k];
        #pragma unroll
        for (int r = 0; r < 8; r++) acc[r] += yv * __ldg(&A[(size_t)r * K + k]);
    }
    #pragma unroll
    for (int r = 0; r < 8; r++) {
        float a = acc[r];
        #pragma unroll
        for (int off = 16; off; off >>= 1) a += __shfl_xor_sync(0xffffffffu, a, off);
        if (lane == 0) Tout[(size_t)row * 8 + r] = a;
    }
}

// ---------------- GEMM (NT) with packed FFMA2 ----------------
// Tile 128x64, BK=16, 256 threads, 8x4 microtile. A stored dup-packed (a,a).
template<int LORA, int RES>
__global__ __launch_bounds__(256) void gemm_nt(
    const float* __restrict__ A, const float* __restrict__ W,
    const float* __restrict__ TL, const float* __restrict__ BL,
    const float* __restrict__ R, float* __restrict__ C, int N, int K) {
    __shared__ ull   As2[16][130];
    __shared__ float Ws [16][68];
    const int bm = blockIdx.y * 128, bn = blockIdx.x * 64;
    const int tid = threadIdx.x;
    const int tx = tid & 15, ty = tid >> 4;
    const int lr = tid >> 2, lc = (tid & 3) * 4;
    const float* Ag0 = A + (size_t)(bm + lr) * K + lc;
    const float* Ag1 = A + (size_t)(bm + 64 + lr) * K + lc;
    const float* Wg  = W + (size_t)(bn + lr) * K + lc;
    ull acc[8][2] = {};
    for (int k0 = 0; k0 < K; k0 += 16) {
        float4 a0 = *(const float4*)(Ag0 + k0);
        float4 a1 = *(const float4*)(Ag1 + k0);
        float4 w4 = *(const float4*)(Wg  + k0);
        __syncthreads();
        As2[lc+0][lr]      = pack2(a0.x, a0.x); As2[lc+1][lr]      = pack2(a0.y, a0.y);
        As2[lc+2][lr]      = pack2(a0.z, a0.z); As2[lc+3][lr]      = pack2(a0.w, a0.w);
        As2[lc+0][64+lr]   = pack2(a1.x, a1.x); As2[lc+1][64+lr]   = pack2(a1.y, a1.y);
        As2[lc+2][64+lr]   = pack2(a1.z, a1.z); As2[lc+3][64+lr]   = pack2(a1.w, a1.w);
        Ws[lc+0][lr] = w4.x; Ws[lc+1][lr] = w4.y; Ws[lc+2][lr] = w4.z; Ws[lc+3][lr] = w4.w;
        __syncthreads();
        #pragma unroll
        for (int kk = 0; kk < 16; kk++) {
            double2 wd = *(const double2*)&Ws[kk][tx * 4];
            ull w01 = d2l(wd.x), w23 = d2l(wd.y);
            ulonglong2 a01 = *(const ulonglong2*)&As2[kk][ty * 8 + 0];
            ulonglong2 a23 = *(const ulonglong2*)&As2[kk][ty * 8 + 2];
            ulonglong2 a45 = *(const ulonglong2*)&As2[kk][ty * 8 + 4];
            ulonglong2 a67 = *(const ulonglong2*)&As2[kk][ty * 8 + 6];
            FMA2(acc[0][0], a01.x, w01); FMA2(acc[0][1], a01.x, w23);
            FMA2(acc[1][0], a01.y, w01); FMA2(acc[1][1], a01.y, w23);
            FMA2(acc[2][0], a23.x, w01); FMA2(acc[2][1], a23.x, w23);
            FMA2(acc[3][0], a23.y, w01); FMA2(acc[3][1], a23.y, w23);
            FMA2(acc[4][0], a45.x, w01); FMA2(acc[4][1], a45.x, w23);
            FMA2(acc[5][0], a45.y, w01); FMA2(acc[5][1], a45.y, w23);
            FMA2(acc[6][0], a67.x, w01); FMA2(acc[6][1], a67.x, w23);
            FMA2(acc[7][0], a67.y, w01); FMA2(acc[7][1], a67.y, w23);
        }
    }
    float accf[8][4];
    #pragma unroll
    for (int i = 0; i < 8; i++) {
        float2 u0 = unpk2(acc[i][0]), u1 = unpk2(acc[i][1]);
        accf[i][0] = u0.x; accf[i][1] = u0.y; accf[i][2] = u1.x; accf[i][3] = u1.y;
    }
    if (LORA) {
        #pragma unroll
        for (int i = 0; i < 8; i++) {
            const float* tp = TL + (size_t)(bm + ty*8 + i) * 8;
            #pragma unroll
            for (int j = 0; j < 4; j++) {
                const float* bp = BL + (size_t)(bn + tx*4 + j) * 8;
                float d = 0.f;
                #pragma unroll
                for (int r = 0; r < 8; r++) d += tp[r] * bp[r];
                accf[i][j] += 0.125f * d;   // SCALING = 1/R
            }
        }
    }
    #pragma unroll
    for (int i = 0; i < 8; i++) {
        size_t off = (size_t)(bm + ty*8 + i) * N + bn + tx*4;
        float4 c4 = make_float4(accf[i][0], accf[i][1], accf[i][2], accf[i][3]);
        if (RES) {
            float4 r4 = *(const float4*)(R + off);
            c4.x += r4.x; c4.y += r4.y; c4.z += r4.z; c4.w += r4.w;
        }
        *(float4*)(C + off) = c4;
    }
}

// ---------------- T5 relative bucket (exact-integer thresholds) ----------------
__device__ __forceinline__ int rel_bucket(int rel) {
    int b = (rel > 0) ? 16 : 0;
    int ar = rel < 0 ? -rel : rel;
    int t;
    if      (ar <  8) t = ar;
    else if (ar < 12) t = 8;
    else if (ar < 16) t = 9;
    else if (ar < 23) t = 10;
    else if (ar < 32) t = 11;
    else if (ar < 46) t = 12;
    else if (ar < 64) t = 13;
    else if (ar < 91) t = 14;
    else              t = 15;
    return b + t;
}

__global__ void posbias_k(const float* __restrict__ RB, float* __restrict__ out) {
    int idx = blockIdx.x * 256 + threadIdx.x;      // over T*T
    int i = idx >> 11, j = idx & 2047;
    int bu = rel_bucket(j - i);
    const float* rb = RB + bu * H_NUM;
    #pragma unroll
    for (int h = 0; h < H_NUM; h++)
        out[(size_t)h * T_DIM * T_DIM + idx] = __ldg(rb + h);
}

// ---------------- Flash attention with packed FFMA2 ----------------
// smem (dynamic, 100352B): Qs2 [d][qrow] dup (ull, pitch 66), Ps2 [key][qrow] dup,
//                          KS swizzled float [d][key], Vs float [key][d].
#define SMEM_ATTN (2 * 64 * 66 * 8 + 2 * 64 * 64 * 4)

__device__ __forceinline__ int swz(int d, int key) {
    return d * 64 + (key ^ (((d >> 3) & 7) << 3));
}

__global__ __launch_bounds__(256, 2) void attn_k(
    const float* __restrict__ Qg, const float* __restrict__ Kg,
    const float* __restrict__ Vg, const float* __restrict__ bias,
    float* __restrict__ Og) {
    extern __shared__ char sraw[];
    ull*   Qs2 = (ull*)sraw;                 // 64*66
    ull*   Ps2 = Qs2 + 64 * 66;              // 64*66
    float* KS  = (float*)(Ps2 + 64 * 66);    // 64*64 swizzled [d][key]
    float* Vs  = KS + 64 * 64;               // 64*64 [key][d]
    const int tid = threadIdx.x;
    const int tx = tid & 15, ty = tid >> 4;
    const int qt = blockIdx.x, h = blockIdx.y, b = blockIdx.z;
    const int q0 = qt * 64;

    // Load Q, dup-packed [d][qrow], pre-scaled by 1/sqrt(64)
    #pragma unroll
    for (int p = 0; p < 4; p++) {
        int e = p * 1024 + tid * 4;
        int r = e >> 6, d = e & 63;
        float4 q4 = *(const float4*)(Qg + (size_t)(b * T_DIM + q0 + r) * D_DIM + h * 64 + d);
        Qs2[(d+0)*66 + r] = pack2(q4.x*0.125f, q4.x*0.125f);
        Qs2[(d+1)*66 + r] = pack2(q4.y*0.125f, q4.y*0.125f);
        Qs2[(d+2)*66 + r] = pack2(q4.z*0.125f, q4.z*0.125f);
        Qs2[(d+3)*66 + r] = pack2(q4.w*0.125f, q4.w*0.125f);
    }

    ull o2[4][2] = {};
    float m_[4], l_[4];
    #pragma unroll
    for (int i = 0; i < 4; i++) { m_[i] = -1e30f; l_[i] = 0.f; }

    for (int jt = 0; jt < 32; jt++) {
        const int k0 = jt * 64;
        __syncthreads();   // prior phase-2 reads of Ps2/Vs and phase-1 reads of KS done
        #pragma unroll
        for (int p = 0; p < 4; p++) {
            int e = p * 1024 + tid * 4;
            int r = e >> 6, d = e & 63;
            size_t go = (size_t)(b * T_DIM + k0 + r) * D_DIM + h * 64 + d;
            float4 k4 = *(const float4*)(Kg + go);
            KS[swz(d + 0, r)] = k4.x; KS[swz(d + 1, r)] = k4.y;
            KS[swz(d + 2, r)] = k4.z; KS[swz(d + 3, r)] = k4.w;
            *(float4*)&Vs[r * 64 + d] = *(const float4*)(Vg + go);
        }
        __syncthreads();

        // S = (Q/8) @ K^T, packed over key pairs
        ull s2[4][2] = {};
        #pragma unroll 16
        for (int d = 0; d < 64; d++) {
            ulonglong2 q01 = *(const ulonglong2*)&Qs2[d * 66 + ty * 4 + 0];
            ulonglong2 q23 = *(const ulonglong2*)&Qs2[d * 66 + ty * 4 + 2];
            double2 kw = *(const double2*)&KS[swz(d, tx * 4)];
            ull k01 = d2l(kw.x), k23 = d2l(kw.y);
            FMA2(s2[0][0], q01.x, k01); FMA2(s2[0][1], q01.x, k23);
            FMA2(s2[1][0], q01.y, k01); FMA2(s2[1][1], q01.y, k23);
            FMA2(s2[2][0], q23.x, k01); FMA2(s2[2][1], q23.x, k23);
            FMA2(s2[3][0], q23.y, k01); FMA2(s2[3][1], q23.y, k23);
        }
        float s[4][4];
        #pragma unroll
        for (int i = 0; i < 4; i++) {
            float2 u0 = unpk2(s2[i][0]), u1 = unpk2(s2[i][1]);
            s[i][0] = u0.x; s[i][1] = u0.y; s[i][2] = u1.x; s[i][3] = u1.y;
        }
        // + T5 relative position bias (x_mask all-ones)
        #pragma unroll
        for (int i = 0; i < 4; i++) {
            float4 b4 = *(const float4*)(bias +
                ((size_t)h * T_DIM + q0 + ty * 4 + i) * T_DIM + k0 + tx * 4);
            s[i][0] += b4.x; s[i][1] += b4.y; s[i][2] += b4.z; s[i][3] += b4.w;
        }
        // online softmax (row spread across 16 tx lanes)
        #pragma unroll
        for (int i = 0; i < 4; i++) {
            float mx = fmaxf(fmaxf(s[i][0], s[i][1]), fmaxf(s[i][2], s[i][3]));
            #pragma unroll
            for (int off = 8; off; off >>= 1)
                mx = fmaxf(mx, __shfl_xor_sync(0xffffffffu, mx, off));
            float mn = fmaxf(m_[i], mx);
            float corr = __expf(m_[i] - mn);
            m_[i] = mn;
            float rs = 0.f;
            #pragma unroll
            for (int j = 0; j < 4; j++) { s[i][j] = __expf(s[i][j] - mn); rs += s[i][j]; }
            #pragma unroll
            for (int off = 8; off; off >>= 1)
                rs += __shfl_xor_sync(0xffffffffu, rs, off);
            l_[i] = l_[i] * corr + rs;
            ull c2 = pack2(corr, corr);
            MUL2(o2[i][0], c2); MUL2(o2[i][1], c2);
        }
        // store P dup-packed [key][qrow]
        #pragma unroll
        for (int i = 0; i < 4; i++)
            #pragma unroll
            for (int j = 0; j < 4; j++)
                Ps2[(tx * 4 + j) * 66 + (ty * 4 + i)] = pack2(s[i][j], s[i][j]);
        __syncthreads();
        // O += P @ V, packed over dim pairs
        #pragma unroll 16
        for (int k = 0; k < 64; k++) {
            ulonglong2 p01 = *(const ulonglong2*)&Ps2[k * 66 + ty * 4 + 0];
            ulonglong2 p23 = *(const ulonglong2*)&Ps2[k * 66 + ty * 4 + 2];
            double2 vv = *(const double2*)&Vs[k * 64 + tx * 4];
            ull v01 = d2l(vv.x), v23 = d2l(vv.y);
            FMA2(o2[0][0], p01.x, v01); FMA2(o2[0][1], p01.x, v23);
            FMA2(o2[1][0], p01.y, v01); FMA2(o2[1][1], p01.y, v23);
            FMA2(o2[2][0], p23.x, v01); FMA2(o2[2][1], p23.x, v23);
            FMA2(o2[3][0], p23.y, v01); FMA2(o2[3][1], p23.y, v23);
        }
    }
    #pragma unroll
    for (int i = 0; i < 4; i++) {
        float inv = 1.0f / l_[i];
        float2 u0 = unpk2(o2[i][0]), u1 = unpk2(o2[i][1]);
        float4 r4 = make_float4(u0.x*inv, u0.y*inv, u1.x*inv, u1.y*inv);
        *(float4*)(Og + (size_t)(b * T_DIM + q0 + ty * 4 + i) * D_DIM + h * 64 + tx * 4) = r4;
    }
}

// ---------------- GEGLU ----------------
__global__ void geglu_k(const float* __restrict__ Hh, float* __restrict__ G) {
    int idx = blockIdx.x * 256 + threadIdx.x;
    int m = idx >> 9, c = (idx & 511) * 4;
    const float* hrow = Hh + (size_t)m * 4096;
    float4 a = *(const float4*)(hrow + c);
    float4 g = *(const float4*)(hrow + 2048 + c);
    float av[4] = {a.x, a.y, a.z, a.w};
    float gv[4] = {g.x, g.y, g.z, g.w};
    float r[4];
    #pragma unroll
    for (int i = 0; i < 4; i++) {
        float xg = gv[i];
        float t = 0.7978845608028654f * (xg + 0.044715f * xg * xg * xg);
        r[i] = av[i] * 0.5f * xg * (1.0f + tanhf(t));
    }
    *(float4*)(G + (size_t)m * 2048 + c) = make_float4(r[0], r[1], r[2], r[3]);
}

// ---------------- host ----------------
extern "C" void kernel_launch(void* const* d_in, const int* in_sizes, int n_in,
                              void* d_out, int out_size) {
    (void)in_sizes; (void)n_in; (void)out_size;
    const float* x    = (const float*)d_in[0];
    const float* n1w  = (const float*)d_in[3];
    const float* n3w  = (const float*)d_in[4];
    const float* wqW  = (const float*)d_in[5];
    const float* wqA  = (const float*)d_in[6];
    const float* wqB  = (const float*)d_in[7];
    const float* wkW  = (const float*)d_in[8];
    const float* wvW  = (const float*)d_in[9];
    const float* wvA  = (const float*)d_in[10];
    const float* wvB  = (const float*)d_in[11];
    const float* fcW  = (const float*)d_in[12];
    const float* fcA  = (const float*)d_in[13];
    const float* fcB  = (const float*)d_in[14];
    const float* relb = (const float*)d_in[15];
    const float* w1W  = (const float*)d_in[16];
    const float* w1A  = (const float*)d_in[17];
    const float* w1B  = (const float*)d_in[18];
    const float* w2W  = (const float*)d_in[19];
    const float* w2A  = (const float*)d_in[20];
    const float* w2B  = (const float*)d_in[21];

    float* out = (float*)d_out;
    float* pb  = out + (size_t)M_ROWS * D_DIM;   // pos_bias region [H,1,T,T]

    float *y, *q, *k, *v, *o, *x1, *hh, *gl, *ta;
    cudaGetSymbolAddress((void**)&y,  g_y);
    cudaGetSymbolAddress((void**)&q,  g_q);
    cudaGetSymbolAddress((void**)&k,  g_kk);
    cudaGetSymbolAddress((void**)&v,  g_v);
    cudaGetSymbolAddress((void**)&o,  g_o);
    cudaGetSymbolAddress((void**)&x1, g_x1);
    cudaGetSymbolAddress((void**)&hh, g_h);
    cudaGetSymbolAddress((void**)&gl, g_gl);
    cudaGetSymbolAddress((void**)&ta, g_ta);

    cudaFuncSetAttribute(attn_k, cudaFuncAttributeMaxDynamicSharedMemorySize, SMEM_ATTN);

    // 1) pos_bias output (also consumed by attention)
    posbias_k<<<(T_DIM * T_DIM) / 256, 256>>>(relb, pb);
    // 2) attention branch
    rmsnorm_k<<<M_ROWS, 256>>>(x, n1w, y);
    lora_a_k<<<M_ROWS / 8, 256>>>(y, wqA, ta, D_DIM);
    gemm_nt<1, 0><<<dim3(16, 32), 256>>>(y, wqW, ta, wqB, nullptr, q, D_DIM, D_DIM);
    gemm_nt<0, 0><<<dim3(16, 32), 256>>>(y, wkW, nullptr, nullptr, nullptr, k, D_DIM, D_DIM);
    lora_a_k<<<M_ROWS / 8, 256>>>(y, wvA, ta, D_DIM);
    gemm_nt<1, 0><<<dim3(16, 32), 256>>>(y, wvW, ta, wvB, nullptr, v, D_DIM, D_DIM);
    attn_k<<<dim3(32, H_NUM, B_DIM), 256, SMEM_ATTN>>>(q, k, v, pb, o);
    lora_a_k<<<M_ROWS / 8, 256>>>(o, fcA, ta, D_DIM);
    gemm_nt<1, 1><<<dim3(16, 32), 256>>>(o, fcW, ta, fcB, x, x1, D_DIM, D_DIM);
    // 3) GEGLU FFN branch
    rmsnorm_k<<<M_ROWS, 256>>>(x1, n3w, y);
    lora_a_k<<<M_ROWS / 8, 256>>>(y, w1A, ta, D_DIM);
    gemm_nt<1, 0><<<dim3(64, 32), 256>>>(y, w1W, ta, w1B, nullptr, hh, 4 * D_DIM, D_DIM);
    geglu_k<<<(M_ROWS * 512) / 256, 256>>>(hh, gl);
    lora_a_k<<<M_ROWS / 8, 256>>>(gl, w2A, ta, 2 * D_DIM);
    gemm_nt<1, 1><<<dim3(16, 32), 256>>>(gl, w2W, ta, w2B, x1, out, D_DIM, 2 * D_DIM);
}

// round 6
// speedup vs baseline: 2.1227x; 2.1227x over previous
#include <cuda_runtime.h>
#include <cuda_bf16.h>
#include <math.h>
#include <stdint.h>

#define T_DIM 2048
#define D_DIM 1024
#define B_DIM 2
#define H_NUM 16
#define M_ROWS 4096   // B*T

// ---------------- scratch (device globals; no allocation) ----------------
__device__ float g_y [(size_t)M_ROWS * D_DIM];
__device__ float g_q [(size_t)M_ROWS * D_DIM];
__device__ float g_kk[(size_t)M_ROWS * D_DIM];
__device__ float g_v [(size_t)M_ROWS * D_DIM];
__device__ float g_o [(size_t)M_ROWS * D_DIM];
__device__ float g_x1[(size_t)M_ROWS * D_DIM];
__device__ float g_h [(size_t)M_ROWS * 4 * D_DIM];
__device__ float g_gl[(size_t)M_ROWS * 2 * D_DIM];
__device__ float g_ta[(size_t)M_ROWS * 8];
// bf16 split buffers
__device__ __nv_bfloat16 g_ah[(size_t)M_ROWS * 2 * D_DIM];
__device__ __nv_bfloat16 g_al[(size_t)M_ROWS * 2 * D_DIM];
__device__ __nv_bfloat16 g_wh[(size_t)4 * D_DIM * D_DIM];
__device__ __nv_bfloat16 g_wl[(size_t)4 * D_DIM * D_DIM];

// ---------------- PTX helpers (sm_80-era features only) ----------------
__device__ __forceinline__ uint32_t smem_u32(const void* p) {
    uint32_t a;
    asm("{ .reg .u64 t; cvta.to.shared.u64 t, %1; cvt.u32.u64 %0, t; }" : "=r"(a) : "l"(p));
    return a;
}
#define CP_ASYNC16(dst, src) \
    asm volatile("cp.async.cg.shared.global [%0], [%1], 16;" :: "r"(dst), "l"(src))
#define CP_COMMIT()   asm volatile("cp.async.commit_group;" ::: "memory")
#define CP_WAIT(n)    asm volatile("cp.async.wait_group %0;" :: "n"(n) : "memory")
#define LDMATRIX_X4(r0, r1, r2, r3, addr) \
    asm volatile("ldmatrix.sync.aligned.m8n8.x4.shared.b16 {%0,%1,%2,%3}, [%4];" \
        : "=r"(r0), "=r"(r1), "=r"(r2), "=r"(r3) : "r"(addr))
#define MMA_BF16(d, a, b) \
    asm volatile("mma.sync.aligned.m16n8k16.row.col.f32.bf16.bf16.f32 " \
        "{%0,%1,%2,%3}, {%4,%5,%6,%7}, {%8,%9}, {%0,%1,%2,%3};" \
        : "+f"((d)[0]), "+f"((d)[1]), "+f"((d)[2]), "+f"((d)[3]) \
        : "r"((a)[0]), "r"((a)[1]), "r"((a)[2]), "r"((a)[3]), "r"(b0_), "r"(b1_))

__device__ __forceinline__ void mma_bf16(float* d, const uint32_t* a,
                                         uint32_t b0, uint32_t b1) {
    asm volatile("mma.sync.aligned.m16n8k16.row.col.f32.bf16.bf16.f32 "
        "{%0,%1,%2,%3}, {%4,%5,%6,%7}, {%8,%9}, {%0,%1,%2,%3};"
        : "+f"(d[0]), "+f"(d[1]), "+f"(d[2]), "+f"(d[3])
        : "r"(a[0]), "r"(a[1]), "r"(a[2]), "r"(a[3]), "r"(b0), "r"(b1));
}

__device__ __forceinline__ uint32_t swz128(uint32_t off) {
    return off ^ ((off >> 3) & 0x70);
}

// ---------------- fp32 -> (hi, lo) bf16 split ----------------
__global__ void split_k(const float* __restrict__ X, __nv_bfloat16* __restrict__ Hi,
                        __nv_bfloat16* __restrict__ Lo, int n4) {
    int i = blockIdx.x * 256 + threadIdx.x;
    if (i >= n4) return;
    float4 x = ((const float4*)X)[i];
    float xs[4] = {x.x, x.y, x.z, x.w};
    uint32_t hu[4], lu[4];
    #pragma unroll
    for (int j = 0; j < 4; j++) {
        __nv_bfloat16 h = __float2bfloat16_rn(xs[j]);
        float r = xs[j] - __bfloat162float(h);        // exact in fp32
        __nv_bfloat16 l = __float2bfloat16_rn(r);
        hu[j] = (uint32_t)__bfloat16_as_ushort(h);
        lu[j] = (uint32_t)__bfloat16_as_ushort(l);
    }
    ((uint2*)Hi)[i] = make_uint2(hu[0] | (hu[1] << 16), hu[2] | (hu[3] << 16));
    ((uint2*)Lo)[i] = make_uint2(lu[0] | (lu[1] << 16), lu[2] | (lu[3] << 16));
}

// ---------------- HMMA GEMM (NT): C = A*W^T via bf16x3 split ----------------
// CTA 128x128, BK=64 bf16, double-buffered cp.async, 8 warps (2m x 4n),
// warp tile 64x32 = 4x4 m16n8k16 tiles. Tiles SW128-swizzled (128B rows).
#define SM_STAGE  65536           // 4 tiles x 16KB (128 rows x 128B)
#define SMEM_GEMM (2 * SM_STAGE)

template<int LORA, int RES>
__global__ __launch_bounds__(256) void gemm_mma(
    const __nv_bfloat16* __restrict__ Ah, const __nv_bfloat16* __restrict__ Al,
    const __nv_bfloat16* __restrict__ Wh, const __nv_bfloat16* __restrict__ Wl,
    const float* __restrict__ TL, const float* __restrict__ BLg,
    const float* __restrict__ R, float* __restrict__ C, int N, int K) {
    extern __shared__ char sraw[];
    const uint32_t sb = smem_u32(sraw);
    const int tid = threadIdx.x, wid = tid >> 5, lane = tid & 31;
    const int wm = wid >> 2, wn = wid & 3;     // warp 64m x 32n
    const int bm = blockIdx.y * 128, bn = blockIdx.x * 128;

    const __nv_bfloat16* srcs[4] = {
        Ah + (size_t)bm * K, Al + (size_t)bm * K,
        Wh + (size_t)bn * K, Wl + (size_t)bn * K };

    // per-thread fill coords: vec16 index w = tid + i*256, row = w>>3, chunk = w&7
    const int fr = tid >> 3, fc = (tid & 7) * 8;     // row, bf16 col of 16B chunk

    auto fill = [&](int stage, int k0) {
        const uint32_t sbase = sb + stage * SM_STAGE;
        #pragma unroll
        for (int t = 0; t < 4; t++) {
            const __nv_bfloat16* src = srcs[t] + k0 + fc;
            uint32_t dstb = sbase + t * 16384;
            #pragma unroll
            for (int i = 0; i < 4; i++) {
                int r = fr + i * 32;
                uint32_t off = swz128(r * 128 + fc * 2);
                CP_ASYNC16(dstb + off, src + (size_t)r * K);
            }
        }
        CP_COMMIT();
    };

    float acc[4][4][4] = {};
    const int nch = K / 64;

    fill(0, 0);
    for (int ch = 0; ch < nch; ch++) {
        if (ch + 1 < nch) fill((ch + 1) & 1, (ch + 1) * 64);
        if (ch + 1 < nch) CP_WAIT(1); else CP_WAIT(0);
        __syncthreads();
        const uint32_t sbase = sb + (ch & 1) * SM_STAGE;
        #pragma unroll
        for (int ks = 0; ks < 4; ks++) {
            const int kb = ks * 32 + (lane >> 4) * 16;   // byte offset within row
            uint32_t ah[4][4], al[4][4], wh[2][4], wl[2][4];
            #pragma unroll
            for (int mt = 0; mt < 4; mt++) {
                int row = wm * 64 + mt * 16 + (lane & 15);
                uint32_t off = swz128(row * 128 + kb);
                LDMATRIX_X4(ah[mt][0], ah[mt][1], ah[mt][2], ah[mt][3], sbase + off);
                LDMATRIX_X4(al[mt][0], al[mt][1], al[mt][2], al[mt][3], sbase + 16384 + off);
            }
            #pragma unroll
            for (int ng = 0; ng < 2; ng++) {
                int row = wn * 32 + ng * 16 + (lane & 15);
                uint32_t off = swz128(row * 128 + kb);
                LDMATRIX_X4(wh[ng][0], wh[ng][1], wh[ng][2], wh[ng][3], sbase + 32768 + off);
                LDMATRIX_X4(wl[ng][0], wl[ng][1], wl[ng][2], wl[ng][3], sbase + 49152 + off);
            }
            #pragma unroll
            for (int mt = 0; mt < 4; mt++) {
                #pragma unroll
                for (int ng = 0; ng < 2; ng++) {
                    // ntile = 2*ng:   b = {reg0, reg2};  ntile = 2*ng+1: b = {reg1, reg3}
                    mma_bf16(acc[mt][2*ng+0], ah[mt], wh[ng][0], wh[ng][2]);
                    mma_bf16(acc[mt][2*ng+1], ah[mt], wh[ng][1], wh[ng][3]);
                    mma_bf16(acc[mt][2*ng+0], ah[mt], wl[ng][0], wl[ng][2]);
                    mma_bf16(acc[mt][2*ng+1], ah[mt], wl[ng][1], wl[ng][3]);
                    mma_bf16(acc[mt][2*ng+0], al[mt], wh[ng][0], wh[ng][2]);
                    mma_bf16(acc[mt][2*ng+1], al[mt], wh[ng][1], wh[ng][3]);
                }
            }
        }
        __syncthreads();
    }

    // epilogue: registers -> global, LoRA + residual fused
    #pragma unroll
    for (int mt = 0; mt < 4; mt++) {
        #pragma unroll
        for (int h2 = 0; h2 < 2; h2++) {
            int row = bm + wm * 64 + mt * 16 + (lane >> 2) + h2 * 8;
            float tl[8];
            if (LORA) {
                float4 t0 = *(const float4*)(TL + (size_t)row * 8);
                float4 t1 = *(const float4*)(TL + (size_t)row * 8 + 4);
                tl[0]=t0.x; tl[1]=t0.y; tl[2]=t0.z; tl[3]=t0.w;
                tl[4]=t1.x; tl[5]=t1.y; tl[6]=t1.z; tl[7]=t1.w;
            }
            #pragma unroll
            for (int nt = 0; nt < 4; nt++) {
                int col = bn + wn * 32 + nt * 8 + (lane & 3) * 2;
                float v0 = acc[mt][nt][h2 * 2 + 0];
                float v1 = acc[mt][nt][h2 * 2 + 1];
                if (LORA) {
                    const float* b0 = BLg + (size_t)col * 8;
                    float d0 = 0.f, d1 = 0.f;
                    #pragma unroll
                    for (int r = 0; r < 8; r++) {
                        d0 += tl[r] * b0[r];
                        d1 += tl[r] * b0[8 + r];
                    }
                    v0 += 0.125f * d0; v1 += 0.125f * d1;   // SCALING = 1/R
                }
                size_t off = (size_t)row * N + col;
                if (RES) {
                    float2 rr = *(const float2*)(R + off);
                    v0 += rr.x; v1 += rr.y;
                }
                *(float2*)(C + off) = make_float2(v0, v1);
            }
        }
    }
}

// ---------------- RMSNorm ----------------
__global__ void rmsnorm_k(const float* __restrict__ X, const float* __restrict__ W,
                          float* __restrict__ Y) {
    int row = blockIdx.x;
    const float4* x4 = (const float4*)(X + (size_t)row * D_DIM);
    float4 v = x4[threadIdx.x];
    float ss = v.x*v.x + v.y*v.y + v.z*v.z + v.w*v.w;
    #pragma unroll
    for (int off = 16; off; off >>= 1) ss += __shfl_xor_sync(0xffffffffu, ss, off);
    __shared__ float sred[8];
    if ((threadIdx.x & 31) == 0) sred[threadIdx.x >> 5] = ss;
    __syncthreads();
    float tot = 0.f;
    #pragma unroll
    for (int i = 0; i < 8; i++) tot += sred[i];
    float inv = rsqrtf(tot * (1.0f / D_DIM) + 1e-6f);
    float4 w = ((const float4*)W)[threadIdx.x];
    float4 o;
    o.x = v.x * inv * w.x; o.y = v.y * inv * w.y;
    o.z = v.z * inv * w.z; o.w = v.w * inv * w.w;
    ((float4*)(Y + (size_t)row * D_DIM))[threadIdx.x] = o;
}

// ---------------- LoRA A: T[m,r] = sum_k Y[m,k]*A[r,k] ----------------
__global__ void lora_a_k(const float* __restrict__ Y, const float* __restrict__ A,
                         float* __restrict__ Tout, int K) {
    int row  = blockIdx.x * 8 + (threadIdx.x >> 5);
    int lane = threadIdx.x & 31;
    const float* y = Y + (size_t)row * K;
    float acc[8] = {0,0,0,0,0,0,0,0};
    for (int k = lane; k < K; k += 32) {
        float yv = y[k];
        #pragma unroll
        for (int r = 0; r < 8; r++) acc[r] += yv * __ldg(&A[(size_t)r * K + k]);
    }
    #pragma unroll
    for (int r = 0; r < 8; r++) {
        float a = acc[r];
        #pragma unroll
        for (int off = 16; off; off >>= 1) a += __shfl_xor_sync(0xffffffffu, a, off);
        if (lane == 0) Tout[(size_t)row * 8 + r] = a;
    }
}

// ---------------- T5 relative bucket (exact-integer thresholds) ----------------
__device__ __forceinline__ int rel_bucket(int rel) {
    int b = (rel > 0) ? 16 : 0;
    int ar = rel < 0 ? -rel : rel;
    int t;
    if      (ar <  8) t = ar;
    else if (ar < 12) t = 8;
    else if (ar < 16) t = 9;
    else if (ar < 23) t = 10;
    else if (ar < 32) t = 11;
    else if (ar < 46) t = 12;
    else if (ar < 64) t = 13;
    else if (ar < 91) t = 14;
    else              t = 15;
    return b + t;
}

__global__ void posbias_k(const float* __restrict__ RB, float* __restrict__ out) {
    int idx = blockIdx.x * 256 + threadIdx.x;      // over T*T
    int i = idx >> 11, j = idx & 2047;
    int bu = rel_bucket(j - i);
    const float* rb = RB + bu * H_NUM;
    #pragma unroll
    for (int h = 0; h < H_NUM; h++)
        out[(size_t)h * T_DIM * T_DIM + idx] = __ldg(rb + h);
}

// ---------------- Flash attention (R3 scalar version) ----------------
__device__ __forceinline__ int swz(int d, int key) {
    return d * 64 + (key ^ (((d >> 3) & 7) << 3));
}

__global__ __launch_bounds__(256) void attn_k(
    const float* __restrict__ Qg, const float* __restrict__ Kg,
    const float* __restrict__ Vg, const float* __restrict__ bias,
    float* __restrict__ Og) {
    __shared__ float Qs[64 * 64];
    __shared__ float KS[64 * 64];
    __shared__ float Vs[64 * 64];
    const int tid = threadIdx.x;
    const int tx = tid & 15, ty = tid >> 4;
    const int qt = blockIdx.x, h = blockIdx.y, b = blockIdx.z;
    const int q0 = qt * 64;

    #pragma unroll
    for (int p = 0; p < 4; p++) {
        int e = p * 1024 + tid * 4;
        int r = e >> 6, d = e & 63;
        float4 q4 = *(const float4*)(Qg + (size_t)(b * T_DIM + q0 + r) * D_DIM + h * 64 + d);
        Qs[swz(d + 0, r)] = q4.x * 0.125f;
        Qs[swz(d + 1, r)] = q4.y * 0.125f;
        Qs[swz(d + 2, r)] = q4.z * 0.125f;
        Qs[swz(d + 3, r)] = q4.w * 0.125f;
    }

    float m_[4], l_[4], o_[4][4];
    #pragma unroll
    for (int i = 0; i < 4; i++) {
        m_[i] = -1e30f; l_[i] = 0.f;
        #pragma unroll
        for (int j = 0; j < 4; j++) o_[i][j] = 0.f;
    }

    for (int jt = 0; jt < 32; jt++) {
        const int k0 = jt * 64;
        __syncthreads();
        #pragma unroll
        for (int p = 0; p < 4; p++) {
            int e = p * 1024 + tid * 4;
            int r = e >> 6, d = e & 63;
            size_t go = (size_t)(b * T_DIM + k0 + r) * D_DIM + h * 64 + d;
            float4 k4 = *(const float4*)(Kg + go);
            KS[swz(d + 0, r)] = k4.x; KS[swz(d + 1, r)] = k4.y;
            KS[swz(d + 2, r)] = k4.z; KS[swz(d + 3, r)] = k4.w;
            *(float4*)&Vs[r * 64 + d] = *(const float4*)(Vg + go);
        }
        __syncthreads();

        float s[4][4] = {};
        #pragma unroll 16
        for (int d = 0; d < 64; d++) {
            float4 qv = *(const float4*)&Qs[swz(d, ty * 4)];
            float4 kv = *(const float4*)&KS[swz(d, tx * 4)];
            float q_[4] = {qv.x, qv.y, qv.z, qv.w};
            float k_[4] = {kv.x, kv.y, kv.z, kv.w};
            #pragma unroll
            for (int i = 0; i < 4; i++)
                #pragma unroll
                for (int j = 0; j < 4; j++) s[i][j] += q_[i] * k_[j];
        }
        #pragma unroll
        for (int i = 0; i < 4; i++) {
            float4 b4 = *(const float4*)(bias +
                ((size_t)h * T_DIM + q0 + ty * 4 + i) * T_DIM + k0 + tx * 4);
            s[i][0] += b4.x; s[i][1] += b4.y; s[i][2] += b4.z; s[i][3] += b4.w;
        }
        #pragma unroll
        for (int i = 0; i < 4; i++) {
            float mx = fmaxf(fmaxf(s[i][0], s[i][1]), fmaxf(s[i][2], s[i][3]));
            #pragma unroll
            for (int off = 8; off; off >>= 1)
                mx = fmaxf(mx, __shfl_xor_sync(0xffffffffu, mx, off));
            float mn = fmaxf(m_[i], mx);
            float corr = __expf(m_[i] - mn);
            m_[i] = mn;
            float rs = 0.f;
            #pragma unroll
            for (int j = 0; j < 4; j++) { s[i][j] = __expf(s[i][j] - mn); rs += s[i][j]; }
            #pragma unroll
            for (int off = 8; off; off >>= 1)
                rs += __shfl_xor_sync(0xffffffffu, rs, off);
            l_[i] = l_[i] * corr + rs;
            #pragma unroll
            for (int j = 0; j < 4; j++) o_[i][j] *= corr;
        }
        __syncthreads();
        #pragma unroll
        for (int i = 0; i < 4; i++)
            #pragma unroll
            for (int j = 0; j < 4; j++)
                KS[swz(tx * 4 + j, ty * 4 + i)] = s[i][j];
        __syncthreads();
        #pragma unroll 16
        for (int k = 0; k < 64; k++) {
            float4 pv = *(const float4*)&KS[swz(k, ty * 4)];
            float4 vv = *(const float4*)&Vs[k * 64 + tx * 4];
            float p_[4] = {pv.x, pv.y, pv.z, pv.w};
            float v_[4] = {vv.x, vv.y, vv.z, vv.w};
            #pragma unroll
            for (int i = 0; i < 4; i++)
                #pragma unroll
                for (int j = 0; j < 4; j++) o_[i][j] += p_[i] * v_[j];
        }
    }
    #pragma unroll
    for (int i = 0; i < 4; i++) {
        float inv = 1.0f / l_[i];
        float4 r4 = make_float4(o_[i][0]*inv, o_[i][1]*inv, o_[i][2]*inv, o_[i][3]*inv);
        *(float4*)(Og + (size_t)(b * T_DIM + q0 + ty * 4 + i) * D_DIM + h * 64 + tx * 4) = r4;
    }
}

// ---------------- GEGLU ----------------
__global__ void geglu_k(const float* __restrict__ Hh, float* __restrict__ G) {
    int idx = blockIdx.x * 256 + threadIdx.x;
    int m = idx >> 9, c = (idx & 511) * 4;
    const float* hrow = Hh + (size_t)m * 4096;
    float4 a = *(const float4*)(hrow + c);
    float4 g = *(const float4*)(hrow + 2048 + c);
    float av[4] = {a.x, a.y, a.z, a.w};
    float gv[4] = {g.x, g.y, g.z, g.w};
    float r[4];
    #pragma unroll
    for (int i = 0; i < 4; i++) {
        float xg = gv[i];
        float t = 0.7978845608028654f * (xg + 0.044715f * xg * xg * xg);
        r[i] = av[i] * 0.5f * xg * (1.0f + tanhf(t));
    }
    *(float4*)(G + (size_t)m * 2048 + c) = make_float4(r[0], r[1], r[2], r[3]);
}

// ---------------- host ----------------
extern "C" void kernel_launch(void* const* d_in, const int* in_sizes, int n_in,
                              void* d_out, int out_size) {
    (void)in_sizes; (void)n_in; (void)out_size;
    const float* x    = (const float*)d_in[0];
    const float* n1w  = (const float*)d_in[3];
    const float* n3w  = (const float*)d_in[4];
    const float* wqW  = (const float*)d_in[5];
    const float* wqA  = (const float*)d_in[6];
    const float* wqB  = (const float*)d_in[7];
    const float* wkW  = (const float*)d_in[8];
    const float* wvW  = (const float*)d_in[9];
    const float* wvA  = (const float*)d_in[10];
    const float* wvB  = (const float*)d_in[11];
    const float* fcW  = (const float*)d_in[12];
    const float* fcA  = (const float*)d_in[13];
    const float* fcB  = (const float*)d_in[14];
    const float* relb = (const float*)d_in[15];
    const float* w1W  = (const float*)d_in[16];
    const float* w1A  = (const float*)d_in[17];
    const float* w1B  = (const float*)d_in[18];
    const float* w2W  = (const float*)d_in[19];
    const float* w2A  = (const float*)d_in[20];
    const float* w2B  = (const float*)d_in[21];

    float* out = (float*)d_out;
    float* pb  = out + (size_t)M_ROWS * D_DIM;   // pos_bias region [H,1,T,T]

    float *y, *q, *k, *v, *o, *x1, *hh, *gl, *ta;
    __nv_bfloat16 *ah, *al, *wh, *wl;
    cudaGetSymbolAddress((void**)&y,  g_y);
    cudaGetSymbolAddress((void**)&q,  g_q);
    cudaGetSymbolAddress((void**)&k,  g_kk);
    cudaGetSymbolAddress((void**)&v,  g_v);
    cudaGetSymbolAddress((void**)&o,  g_o);
    cudaGetSymbolAddress((void**)&x1, g_x1);
    cudaGetSymbolAddress((void**)&hh, g_h);
    cudaGetSymbolAddress((void**)&gl, g_gl);
    cudaGetSymbolAddress((void**)&ta, g_ta);
    cudaGetSymbolAddress((void**)&ah, g_ah);
    cudaGetSymbolAddress((void**)&al, g_al);
    cudaGetSymbolAddress((void**)&wh, g_wh);
    cudaGetSymbolAddress((void**)&wl, g_wl);

    cudaFuncSetAttribute(gemm_mma<1,0>, cudaFuncAttributeMaxDynamicSharedMemorySize, SMEM_GEMM);
    cudaFuncSetAttribute(gemm_mma<0,0>, cudaFuncAttributeMaxDynamicSharedMemorySize, SMEM_GEMM);
    cudaFuncSetAttribute(gemm_mma<1,1>, cudaFuncAttributeMaxDynamicSharedMemorySize, SMEM_GEMM);

    const int nDD  = M_ROWS * D_DIM / 4;          // 1M float4
    // 1) pos_bias output (also consumed by attention)
    posbias_k<<<(T_DIM * T_DIM) / 256, 256>>>(relb, pb);
    // 2) attention branch
    rmsnorm_k<<<M_ROWS, 256>>>(x, n1w, y);
    split_k<<<nDD / 256, 256>>>(y, ah, al, nDD);
    lora_a_k<<<M_ROWS / 8, 256>>>(y, wqA, ta, D_DIM);
    split_k<<<(D_DIM * D_DIM / 4) / 256, 256>>>(wqW, wh, wl, D_DIM * D_DIM / 4);
    gemm_mma<1,0><<<dim3(8, 32), 256, SMEM_GEMM>>>(ah, al, wh, wl, ta, wqB, nullptr, q, D_DIM, D_DIM);
    split_k<<<(D_DIM * D_DIM / 4) / 256, 256>>>(wkW, wh, wl, D_DIM * D_DIM / 4);
    gemm_mma<0,0><<<dim3(8, 32), 256, SMEM_GEMM>>>(ah, al, wh, wl, nullptr, nullptr, nullptr, k, D_DIM, D_DIM);
    lora_a_k<<<M_ROWS / 8, 256>>>(y, wvA, ta, D_DIM);
    split_k<<<(D_DIM * D_DIM / 4) / 256, 256>>>(wvW, wh, wl, D_DIM * D_DIM / 4);
    gemm_mma<1,0><<<dim3(8, 32), 256, SMEM_GEMM>>>(ah, al, wh, wl, ta, wvB, nullptr, v, D_DIM, D_DIM);
    attn_k<<<dim3(32, H_NUM, B_DIM), 256>>>(q, k, v, pb, o);
    lora_a_k<<<M_ROWS / 8, 256>>>(o, fcA, ta, D_DIM);
    split_k<<<nDD / 256, 256>>>(o, ah, al, nDD);
    split_k<<<(D_DIM * D_DIM / 4) / 256, 256>>>(fcW, wh, wl, D_DIM * D_DIM / 4);
    gemm_mma<1,1><<<dim3(8, 32), 256, SMEM_GEMM>>>(ah, al, wh, wl, ta, fcB, x, x1, D_DIM, D_DIM);
    // 3) GEGLU FFN branch
    rmsnorm_k<<<M_ROWS, 256>>>(x1, n3w, y);
    lora_a_k<<<M_ROWS / 8, 256>>>(y, w1A, ta, D_DIM);
    split_k<<<nDD / 256, 256>>>(y, ah, al, nDD);
    split_k<<<(4 * D_DIM * D_DIM / 4) / 256, 256>>>(w1W, wh, wl, 4 * D_DIM * D_DIM / 4);
    gemm_mma<1,0><<<dim3(32, 32), 256, SMEM_GEMM>>>(ah, al, wh, wl, ta, w1B, nullptr, hh, 4 * D_DIM, D_DIM);
    geglu_k<<<(M_ROWS * 512) / 256, 256>>>(hh, gl);
    lora_a_k<<<M_ROWS / 8, 256>>>(gl, w2A, ta, 2 * D_DIM);
    split_k<<<(M_ROWS * 2 * D_DIM / 4) / 256, 256>>>(gl, ah, al, M_ROWS * 2 * D_DIM / 4);
    split_k<<<(2 * D_DIM * D_DIM / 4) / 256, 256>>>(w2W, wh, wl, 2 * D_DIM * D_DIM / 4);
    gemm_mma<1,1><<<dim3(8, 32), 256, SMEM_GEMM>>>(ah, al, wh, wl, ta, w2B, x1, out, D_DIM, 2 * D_DIM);
}

// round 12
// speedup vs baseline: 4.3948x; 2.0703x over previous
#include <cuda_runtime.h>
#include <cuda_bf16.h>
#include <math.h>
#include <stdint.h>

#define T_DIM 2048
#define D_DIM 1024
#define B_DIM 2
#define H_NUM 16
#define M_ROWS 4096   // B*T

// ---------------- scratch (device globals; no allocation) ----------------
__device__ float g_y [(size_t)M_ROWS * D_DIM];
__device__ float g_q [(size_t)M_ROWS * D_DIM];   // holds bf16 q (reinterpreted)
__device__ float g_kk[(size_t)M_ROWS * D_DIM];   // holds bf16 k
__device__ float g_v [(size_t)M_ROWS * D_DIM];   // holds bf16 v
__device__ float g_o [(size_t)M_ROWS * D_DIM];
__device__ float g_x1[(size_t)M_ROWS * D_DIM];
__device__ float g_h [(size_t)M_ROWS * 4 * D_DIM];
__device__ float g_gl[(size_t)M_ROWS * 2 * D_DIM];
__device__ float g_ta[(size_t)M_ROWS * 8];
__device__ __nv_bfloat16 g_ah[(size_t)M_ROWS * 2 * D_DIM];
__device__ __nv_bfloat16 g_al[(size_t)M_ROWS * 2 * D_DIM];
__device__ __nv_bfloat16 g_wh[(size_t)4 * D_DIM * D_DIM];
__device__ __nv_bfloat16 g_wl[(size_t)4 * D_DIM * D_DIM];

// ---------------- PTX helpers (sm_80-era features only) ----------------
__device__ __forceinline__ uint32_t smem_u32(const void* p) {
    uint32_t a;
    asm("{ .reg .u64 t; cvta.to.shared.u64 t, %1; cvt.u32.u64 %0, t; }" : "=r"(a) : "l"(p));
    return a;
}
#define CP_ASYNC16(dst, src) \
    asm volatile("cp.async.cg.shared.global [%0], [%1], 16;" :: "r"(dst), "l"(src))
#define CP_COMMIT()   asm volatile("cp.async.commit_group;" ::: "memory")
#define CP_WAIT(n)    asm volatile("cp.async.wait_group %0;" :: "n"(n) : "memory")
#define LDMATRIX_X4(r0, r1, r2, r3, addr) \
    asm volatile("ldmatrix.sync.aligned.m8n8.x4.shared.b16 {%0,%1,%2,%3}, [%4];" \
        : "=r"(r0), "=r"(r1), "=r"(r2), "=r"(r3) : "r"(addr))
#define LDMATRIX_X4_T(r0, r1, r2, r3, addr) \
    asm volatile("ldmatrix.sync.aligned.m8n8.x4.trans.shared.b16 {%0,%1,%2,%3}, [%4];" \
        : "=r"(r0), "=r"(r1), "=r"(r2), "=r"(r3) : "r"(addr))

__device__ __forceinline__ void mma_bf16(float* d, const uint32_t* a,
                                         uint32_t b0, uint32_t b1) {
    asm volatile("mma.sync.aligned.m16n8k16.row.col.f32.bf16.bf16.f32 "
        "{%0,%1,%2,%3}, {%4,%5,%6,%7}, {%8,%9}, {%0,%1,%2,%3};"
        : "+f"(d[0]), "+f"(d[1]), "+f"(d[2]), "+f"(d[3])
        : "r"(a[0]), "r"(a[1]), "r"(a[2]), "r"(a[3]), "r"(b0), "r"(b1));
}
__device__ __forceinline__ uint32_t swz128(uint32_t off) {
    return off ^ ((off >> 3) & 0x70);
}
// pack two fp32 into bf16x2: lo in lower half, hi in upper half
__device__ __forceinline__ uint32_t packbf(float lo, float hi) {
    uint32_t r;
    asm("cvt.rn.bf16x2.f32 %0, %1, %2;" : "=r"(r) : "f"(hi), "f"(lo));
    return r;
}

// ---------------- fp32 -> (hi, lo) bf16 split ----------------
__global__ void split_k(const float* __restrict__ X, __nv_bfloat16* __restrict__ Hi,
                        __nv_bfloat16* __restrict__ Lo, int n4) {
    int i = blockIdx.x * 256 + threadIdx.x;
    if (i >= n4) return;
    float4 x = ((const float4*)X)[i];
    float xs[4] = {x.x, x.y, x.z, x.w};
    uint32_t hu[4], lu[4];
    #pragma unroll
    for (int j = 0; j < 4; j++) {
        __nv_bfloat16 h = __float2bfloat16_rn(xs[j]);
        float r = xs[j] - __bfloat162float(h);
        __nv_bfloat16 l = __float2bfloat16_rn(r);
        hu[j] = (uint32_t)__bfloat16_as_ushort(h);
        lu[j] = (uint32_t)__bfloat16_as_ushort(l);
    }
    ((uint2*)Hi)[i] = make_uint2(hu[0] | (hu[1] << 16), hu[2] | (hu[3] << 16));
    ((uint2*)Lo)[i] = make_uint2(lu[0] | (lu[1] << 16), lu[2] | (lu[3] << 16));
}

// ---------------- HMMA GEMM (NT): C = A*W^T ----------------
// CTA 128x128, BK=64, double-buffered cp.async, 8 warps (2m x 4n).
// SPLIT=1: bf16x3 (Ah*Wh + Ah*Wl + Al*Wh); SPLIT=0: Ah*Wh only.
#define SM_STAGE  65536
#define SMEM_GEMM (2 * SM_STAGE)

template<int LORA, int RES, int SPLIT, int OUTBF16>
__global__ __launch_bounds__(256) void gemm_mma(
    const __nv_bfloat16* __restrict__ Ah, const __nv_bfloat16* __restrict__ Al,
    const __nv_bfloat16* __restrict__ Wh, const __nv_bfloat16* __restrict__ Wl,
    const float* __restrict__ TL, const float* __restrict__ BLg,
    const float* __restrict__ R, void* __restrict__ Cv, int N, int K) {
    extern __shared__ char sraw[];
    const uint32_t sb = smem_u32(sraw);
    const int tid = threadIdx.x, wid = tid >> 5, lane = tid & 31;
    const int wm = wid >> 2, wn = wid & 3;
    const int bm = blockIdx.y * 128, bn = blockIdx.x * 128;

    const __nv_bfloat16* srcs[4] = {
        Ah + (size_t)bm * K, Al + (size_t)bm * K,
        Wh + (size_t)bn * K, Wl + (size_t)bn * K };

    const int fr = tid >> 3, fc = (tid & 7) * 8;

    auto fill = [&](int stage, int k0) {
        const uint32_t sbase = sb + stage * SM_STAGE;
        #pragma unroll
        for (int t = 0; t < 4; t++) {
            if (!SPLIT && (t == 1 || t == 3)) continue;
            const __nv_bfloat16* src = srcs[t] + k0 + fc;
            uint32_t dstb = sbase + t * 16384;
            #pragma unroll
            for (int i = 0; i < 4; i++) {
                int r = fr + i * 32;
                uint32_t off = swz128(r * 128 + fc * 2);
                CP_ASYNC16(dstb + off, src + (size_t)r * K);
            }
        }
        CP_COMMIT();
    };

    float acc[4][4][4] = {};
    const int nch = K / 64;

    fill(0, 0);
    for (int ch = 0; ch < nch; ch++) {
        if (ch + 1 < nch) { fill((ch + 1) & 1, (ch + 1) * 64); CP_WAIT(1); }
        else CP_WAIT(0);
        __syncthreads();
        const uint32_t sbase = sb + (ch & 1) * SM_STAGE;
        #pragma unroll
        for (int ks = 0; ks < 4; ks++) {
            const int kb = ks * 32 + (lane >> 4) * 16;
            uint32_t ah[4][4], al[4][4], wh[2][4], wl[2][4];
            #pragma unroll
            for (int mt = 0; mt < 4; mt++) {
                int row = wm * 64 + mt * 16 + (lane & 15);
                uint32_t off = swz128(row * 128 + kb);
                LDMATRIX_X4(ah[mt][0], ah[mt][1], ah[mt][2], ah[mt][3], sbase + off);
                if (SPLIT)
                    LDMATRIX_X4(al[mt][0], al[mt][1], al[mt][2], al[mt][3], sbase + 16384 + off);
            }
            #pragma unroll
            for (int ng = 0; ng < 2; ng++) {
                int row = wn * 32 + ng * 16 + (lane & 15);
                uint32_t off = swz128(row * 128 + kb);
                LDMATRIX_X4(wh[ng][0], wh[ng][1], wh[ng][2], wh[ng][3], sbase + 32768 + off);
                if (SPLIT)
                    LDMATRIX_X4(wl[ng][0], wl[ng][1], wl[ng][2], wl[ng][3], sbase + 49152 + off);
            }
            #pragma unroll
            for (int mt = 0; mt < 4; mt++) {
                #pragma unroll
                for (int ng = 0; ng < 2; ng++) {
                    mma_bf16(acc[mt][2*ng+0], ah[mt], wh[ng][0], wh[ng][2]);
                    mma_bf16(acc[mt][2*ng+1], ah[mt], wh[ng][1], wh[ng][3]);
                    if (SPLIT) {
                        mma_bf16(acc[mt][2*ng+0], ah[mt], wl[ng][0], wl[ng][2]);
                        mma_bf16(acc[mt][2*ng+1], ah[mt], wl[ng][1], wl[ng][3]);
                        mma_bf16(acc[mt][2*ng+0], al[mt], wh[ng][0], wh[ng][2]);
                        mma_bf16(acc[mt][2*ng+1], al[mt], wh[ng][1], wh[ng][3]);
                    }
                }
            }
        }
        __syncthreads();
    }

    float* C = (float*)Cv;
    __nv_bfloat16* Cb = (__nv_bfloat16*)Cv;
    #pragma unroll
    for (int mt = 0; mt < 4; mt++) {
        #pragma unroll
        for (int h2 = 0; h2 < 2; h2++) {
            int row = bm + wm * 64 + mt * 16 + (lane >> 2) + h2 * 8;
            float tl[8];
            if (LORA) {
                float4 t0 = *(const float4*)(TL + (size_t)row * 8);
                float4 t1 = *(const float4*)(TL + (size_t)row * 8 + 4);
                tl[0]=t0.x; tl[1]=t0.y; tl[2]=t0.z; tl[3]=t0.w;
                tl[4]=t1.x; tl[5]=t1.y; tl[6]=t1.z; tl[7]=t1.w;
            }
            #pragma unroll
            for (int nt = 0; nt < 4; nt++) {
                int col = bn + wn * 32 + nt * 8 + (lane & 3) * 2;
                float v0 = acc[mt][nt][h2 * 2 + 0];
                float v1 = acc[mt][nt][h2 * 2 + 1];
                if (LORA) {
                    const float* b0 = BLg + (size_t)col * 8;
                    float d0 = 0.f, d1 = 0.f;
                    #pragma unroll
                    for (int r = 0; r < 8; r++) {
                        d0 += tl[r] * b0[r];
                        d1 += tl[r] * b0[8 + r];
                    }
                    v0 += 0.125f * d0; v1 += 0.125f * d1;
                }
                size_t off = (size_t)row * N + col;
                if (RES) {
                    float2 rr = *(const float2*)(R + off);
                    v0 += rr.x; v1 += rr.y;
                }
                if (OUTBF16) {
                    *(uint32_t*)(Cb + off) = packbf(v0, v1);
                } else {
                    *(float2*)(C + off) = make_float2(v0, v1);
                }
            }
        }
    }
}

// ---------------- RMSNorm ----------------
__global__ void rmsnorm_k(const float* __restrict__ X, const float* __restrict__ W,
                          float* __restrict__ Y) {
    int row = blockIdx.x;
    const float4* x4 = (const float4*)(X + (size_t)row * D_DIM);
    float4 v = x4[threadIdx.x];
    float ss = v.x*v.x + v.y*v.y + v.z*v.z + v.w*v.w;
    #pragma unroll
    for (int off = 16; off; off >>= 1) ss += __shfl_xor_sync(0xffffffffu, ss, off);
    __shared__ float sred[8];
    if ((threadIdx.x & 31) == 0) sred[threadIdx.x >> 5] = ss;
    __syncthreads();
    float tot = 0.f;
    #pragma unroll
    for (int i = 0; i < 8; i++) tot += sred[i];
    float inv = rsqrtf(tot * (1.0f / D_DIM) + 1e-6f);
    float4 w = ((const float4*)W)[threadIdx.x];
    float4 o;
    o.x = v.x * inv * w.x; o.y = v.y * inv * w.y;
    o.z = v.z * inv * w.z; o.w = v.w * inv * w.w;
    ((float4*)(Y + (size_t)row * D_DIM))[threadIdx.x] = o;
}

// ---------------- LoRA A ----------------
__global__ void lora_a_k(const float* __restrict__ Y, const float* __restrict__ A,
                         float* __restrict__ Tout, int K) {
    int row  = blockIdx.x * 8 + (threadIdx.x >> 5);
    int lane = threadIdx.x & 31;
    const float* y = Y + (size_t)row * K;
    float acc[8] = {0,0,0,0,0,0,0,0};
    for (int k = lane; k < K; k += 32) {
        float yv = y[k];
        #pragma unroll
        for (int r = 0; r < 8; r++) acc[r] += yv * __ldg(&A[(size_t)r * K + k]);
    }
    #pragma unroll
    for (int r = 0; r < 8; r++) {
        float a = acc[r];
        #pragma unroll
        for (int off = 16; off; off >>= 1) a += __shfl_xor_sync(0xffffffffu, a, off);
        if (lane == 0) Tout[(size_t)row * 8 + r] = a;
    }
}

// ---------------- T5 relative bucket ----------------
__device__ __forceinline__ int rel_bucket(int rel) {
    int b = (rel > 0) ? 16 : 0;
    int ar = rel < 0 ? -rel : rel;
    int t;
    if      (ar <  8) t = ar;
    else if (ar < 12) t = 8;
    else if (ar < 16) t = 9;
    else if (ar < 23) t = 10;
    else if (ar < 32) t = 11;
    else if (ar < 46) t = 12;
    else if (ar < 64) t = 13;
    else if (ar < 91) t = 14;
    else              t = 15;
    return b + t;
}

__global__ void posbias_k(const float* __restrict__ RB, float* __restrict__ out) {
    int idx = blockIdx.x * 256 + threadIdx.x;
    int i = idx >> 11, j = idx & 2047;
    int bu = rel_bucket(j - i);
    const float* rb = RB + bu * H_NUM;
    #pragma unroll
    for (int h = 0; h < H_NUM; h++)
        out[(size_t)h * T_DIM * T_DIM + idx] = __ldg(rb + h);
}

// ---------------- HMMA flash attention (bf16 QKV, fp32 accum) ----------------
// 128 threads = 4 warps, each warp m16 x n64 keys. Bias from smem LUT.
// smem: Qs 8KB | K/V stages 2x16KB | LUT 16KB  = 57344B
#define SMEM_ATTN 57344

__global__ __launch_bounds__(128) void attn_mma(
    const __nv_bfloat16* __restrict__ Qg, const __nv_bfloat16* __restrict__ Kg,
    const __nv_bfloat16* __restrict__ Vg, const float* __restrict__ relb,
    float* __restrict__ Og) {
    extern __shared__ char sraw[];
    const uint32_t sb = smem_u32(sraw);
    float* LUT = (float*)(sraw + 40960);
    const int tid = threadIdx.x, wid = tid >> 5, lane = tid & 31;
    const int q0 = blockIdx.x * 64, h = blockIdx.y, b = blockIdx.z;

    // bias LUT: delta -> rel_bias[bucket(delta)][h], delta = key - query
    for (int i = tid; i < 4095; i += 128)
        LUT[i] = __ldg(&relb[rel_bucket(i - 2047) * H_NUM + h]);

    // Q tile: 64 rows x 64 bf16 (128B rows, SW128-swizzled)
    const __nv_bfloat16* Qrow = Qg + ((size_t)(b * T_DIM + q0)) * D_DIM + h * 64;
    #pragma unroll
    for (int i = 0; i < 4; i++) {
        int w = tid + i * 128;
        int r = w >> 3, c8 = (w & 7) * 8;
        CP_ASYNC16(sb + swz128(r * 128 + c8 * 2), Qrow + (size_t)r * D_DIM + c8);
    }
    auto fillkv = [&](int st, int kt) {
        const __nv_bfloat16* Kr = Kg + ((size_t)(b * T_DIM + kt * 64)) * D_DIM + h * 64;
        const __nv_bfloat16* Vr = Vg + ((size_t)(b * T_DIM + kt * 64)) * D_DIM + h * 64;
        uint32_t base = sb + 8192 + st * 16384;
        #pragma unroll
        for (int i = 0; i < 4; i++) {
            int w = tid + i * 128;
            int r = w >> 3, c8 = (w & 7) * 8;
            uint32_t off = swz128(r * 128 + c8 * 2);
            CP_ASYNC16(base + off, Kr + (size_t)r * D_DIM + c8);
            CP_ASYNC16(base + 8192 + off, Vr + (size_t)r * D_DIM + c8);
        }
    };
    fillkv(0, 0);
    CP_COMMIT();

    float oacc[8][4] = {};
    float m0 = -1e30f, m1 = -1e30f, l0 = 0.f, l1 = 0.f;
    const int qrow = q0 + wid * 16 + (lane >> 2);

    for (int jt = 0; jt < 32; jt++) {
        if (jt + 1 < 32) { fillkv((jt + 1) & 1, jt + 1); CP_COMMIT(); CP_WAIT(1); }
        else CP_WAIT(0);
        __syncthreads();
        const uint32_t Kb = sb + 8192 + (jt & 1) * 16384;
        const uint32_t Vb = Kb + 8192;

        // S = Q @ K^T
        float s[8][4] = {};
        #pragma unroll
        for (int kc = 0; kc < 4; kc++) {
            const int kb = kc * 32 + (lane >> 4) * 16;
            uint32_t qf[4];
            LDMATRIX_X4(qf[0], qf[1], qf[2], qf[3],
                        sb + swz128((wid * 16 + (lane & 15)) * 128 + kb));
            #pragma unroll
            for (int ng = 0; ng < 4; ng++) {
                uint32_t kf[4];
                LDMATRIX_X4(kf[0], kf[1], kf[2], kf[3],
                            Kb + swz128((ng * 16 + (lane & 15)) * 128 + kb));
                mma_bf16(s[2*ng+0], qf, kf[0], kf[2]);
                mma_bf16(s[2*ng+1], qf, kf[1], kf[3]);
            }
        }
        // scale + bias + online softmax (rows r and r+8)
        const int db0 = jt * 64 - qrow + 2047 + 2 * (lane & 3);
        float mx0 = -1e30f, mx1 = -1e30f;
        #pragma unroll
        for (int t = 0; t < 8; t++) {
            int ib = db0 + t * 8;
            s[t][0] = s[t][0] * 0.125f + LUT[ib];
            s[t][1] = s[t][1] * 0.125f + LUT[ib + 1];
            s[t][2] = s[t][2] * 0.125f + LUT[ib - 8];
            s[t][3] = s[t][3] * 0.125f + LUT[ib - 7];
            mx0 = fmaxf(mx0, fmaxf(s[t][0], s[t][1]));
            mx1 = fmaxf(mx1, fmaxf(s[t][2], s[t][3]));
        }
        mx0 = fmaxf(mx0, __shfl_xor_sync(0xffffffffu, mx0, 1));
        mx0 = fmaxf(mx0, __shfl_xor_sync(0xffffffffu, mx0, 2));
        mx1 = fmaxf(mx1, __shfl_xor_sync(0xffffffffu, mx1, 1));
        mx1 = fmaxf(mx1, __shfl_xor_sync(0xffffffffu, mx1, 2));
        float nm0 = fmaxf(m0, mx0), nm1 = fmaxf(m1, mx1);
        float c0 = __expf(m0 - nm0), c1 = __expf(m1 - nm1);
        m0 = nm0; m1 = nm1;
        float rs0 = 0.f, rs1 = 0.f;
        #pragma unroll
        for (int t = 0; t < 8; t++) {
            s[t][0] = __expf(s[t][0] - nm0); rs0 += s[t][0];
            s[t][1] = __expf(s[t][1] - nm0); rs0 += s[t][1];
            s[t][2] = __expf(s[t][2] - nm1); rs1 += s[t][2];
            s[t][3] = __expf(s[t][3] - nm1); rs1 += s[t][3];
        }
        rs0 += __shfl_xor_sync(0xffffffffu, rs0, 1);
        rs0 += __shfl_xor_sync(0xffffffffu, rs0, 2);
        rs1 += __shfl_xor_sync(0xffffffffu, rs1, 1);
        rs1 += __shfl_xor_sync(0xffffffffu, rs1, 2);
        l0 = l0 * c0 + rs0; l1 = l1 * c1 + rs1;
        #pragma unroll
        for (int t = 0; t < 8; t++) {
            oacc[t][0] *= c0; oacc[t][1] *= c0;
            oacc[t][2] *= c1; oacc[t][3] *= c1;
        }
        // O += P @ V (P fragments from accumulators in-register)
        #pragma unroll
        for (int c = 0; c < 4; c++) {
            uint32_t af[4];
            af[0] = packbf(s[2*c+0][0], s[2*c+0][1]);
            af[1] = packbf(s[2*c+0][2], s[2*c+0][3]);
            af[2] = packbf(s[2*c+1][0], s[2*c+1][1]);
            af[3] = packbf(s[2*c+1][2], s[2*c+1][3]);
            #pragma unroll
            for (int j = 0; j < 4; j++) {
                uint32_t vf[4];
                int row = c * 16 + ((lane >> 4) * 8) + (lane & 7);
                int colb = j * 32 + ((lane >> 3) & 1) * 16;
                LDMATRIX_X4_T(vf[0], vf[1], vf[2], vf[3], Vb + swz128(row * 128 + colb));
                mma_bf16(oacc[2*j+0], af, vf[0], vf[2]);
                mma_bf16(oacc[2*j+1], af, vf[1], vf[3]);
            }
        }
        __syncthreads();
    }
    float inv0 = 1.0f / l0, inv1 = 1.0f / l1;
    size_t row0 = (size_t)(b * T_DIM + qrow) * D_DIM + h * 64;
    size_t row1 = row0 + 8 * D_DIM;
    #pragma unroll
    for (int t = 0; t < 8; t++) {
        int col = t * 8 + (lane & 3) * 2;
        *(float2*)(Og + row0 + col) = make_float2(oacc[t][0] * inv0, oacc[t][1] * inv0);
        *(float2*)(Og + row1 + col) = make_float2(oacc[t][2] * inv1, oacc[t][3] * inv1);
    }
}

// ---------------- GEGLU ----------------
__global__ void geglu_k(const float* __restrict__ Hh, float* __restrict__ G) {
    int idx = blockIdx.x * 256 + threadIdx.x;
    int m = idx >> 9, c = (idx & 511) * 4;
    const float* hrow = Hh + (size_t)m * 4096;
    float4 a = *(const float4*)(hrow + c);
    float4 g = *(const float4*)(hrow + 2048 + c);
    float av[4] = {a.x, a.y, a.z, a.w};
    float gv[4] = {g.x, g.y, g.z, g.w};
    float r[4];
    #pragma unroll
    for (int i = 0; i < 4; i++) {
        float xg = gv[i];
        float t = 0.7978845608028654f * (xg + 0.044715f * xg * xg * xg);
        r[i] = av[i] * 0.5f * xg * (1.0f + tanhf(t));
    }
    *(float4*)(G + (size_t)m * 2048 + c) = make_float4(r[0], r[1], r[2], r[3]);
}

// ---------------- host ----------------
extern "C" void kernel_launch(void* const* d_in, const int* in_sizes, int n_in,
                              void* d_out, int out_size) {
    (void)in_sizes; (void)n_in; (void)out_size;
    const float* x    = (const float*)d_in[0];
    const float* n1w  = (const float*)d_in[3];
    const float* n3w  = (const float*)d_in[4];
    const float* wqW  = (const float*)d_in[5];
    const float* wqA  = (const float*)d_in[6];
    const float* wqB  = (const float*)d_in[7];
    const float* wkW  = (const float*)d_in[8];
    const float* wvW  = (const float*)d_in[9];
    const float* wvA  = (const float*)d_in[10];
    const float* wvB  = (const float*)d_in[11];
    const float* fcW  = (const float*)d_in[12];
    const float* fcA  = (const float*)d_in[13];
    const float* fcB  = (const float*)d_in[14];
    const float* relb = (const float*)d_in[15];
    const float* w1W  = (const float*)d_in[16];
    const float* w1A  = (const float*)d_in[17];
    const float* w1B  = (const float*)d_in[18];
    const float* w2W  = (const float*)d_in[19];
    const float* w2A  = (const float*)d_in[20];
    const float* w2B  = (const float*)d_in[21];

    float* out = (float*)d_out;
    float* pb  = out + (size_t)M_ROWS * D_DIM;

    float *y, *q, *k, *v, *o, *x1, *hh, *gl, *ta;
    __nv_bfloat16 *ah, *al, *wh, *wl;
    cudaGetSymbolAddress((void**)&y,  g_y);
    cudaGetSymbolAddress((void**)&q,  g_q);
    cudaGetSymbolAddress((void**)&k,  g_kk);
    cudaGetSymbolAddress((void**)&v,  g_v);
    cudaGetSymbolAddress((void**)&o,  g_o);
    cudaGetSymbolAddress((void**)&x1, g_x1);
    cudaGetSymbolAddress((void**)&hh, g_h);
    cudaGetSymbolAddress((void**)&gl, g_gl);
    cudaGetSymbolAddress((void**)&ta, g_ta);
    cudaGetSymbolAddress((void**)&ah, g_ah);
    cudaGetSymbolAddress((void**)&al, g_al);
    cudaGetSymbolAddress((void**)&wh, g_wh);
    cudaGetSymbolAddress((void**)&wl, g_wl);
    __nv_bfloat16* qb = (__nv_bfloat16*)q;
    __nv_bfloat16* kb = (__nv_bfloat16*)k;
    __nv_bfloat16* vb = (__nv_bfloat16*)v;

    cudaFuncSetAttribute(gemm_mma<1,0,0,1>, cudaFuncAttributeMaxDynamicSharedMemorySize, SMEM_GEMM);
    cudaFuncSetAttribute(gemm_mma<0,0,0,1>, cudaFuncAttributeMaxDynamicSharedMemorySize, SMEM_GEMM);
    cudaFuncSetAttribute(gemm_mma<1,1,0,0>, cudaFuncAttributeMaxDynamicSharedMemorySize, SMEM_GEMM);
    cudaFuncSetAttribute(gemm_mma<1,0,1,0>, cudaFuncAttributeMaxDynamicSharedMemorySize, SMEM_GEMM);
    cudaFuncSetAttribute(gemm_mma<1,1,1,0>, cudaFuncAttributeMaxDynamicSharedMemorySize, SMEM_GEMM);
    cudaFuncSetAttribute(attn_mma, cudaFuncAttributeMaxDynamicSharedMemorySize, SMEM_ATTN);

    const int nDD = M_ROWS * D_DIM / 4;
    // 1) pos_bias output
    posbias_k<<<(T_DIM * T_DIM) / 256, 256>>>(relb, pb);
    // 2) attention branch
    rmsnorm_k<<<M_ROWS, 256>>>(x, n1w, y);
    split_k<<<nDD / 256, 256>>>(y, ah, al, nDD);
    lora_a_k<<<M_ROWS / 8, 256>>>(y, wqA, ta, D_DIM);
    split_k<<<(D_DIM * D_DIM / 4) / 256, 256>>>(wqW, wh, wl, D_DIM * D_DIM / 4);
    gemm_mma<1,0,0,1><<<dim3(8, 32), 256, SMEM_GEMM>>>(ah, al, wh, wl, ta, wqB, nullptr, qb, D_DIM, D_DIM);
    split_k<<<(D_DIM * D_DIM / 4) / 256, 256>>>(wkW, wh, wl, D_DIM * D_DIM / 4);
    gemm_mma<0,0,0,1><<<dim3(8, 32), 256, SMEM_GEMM>>>(ah, al, wh, wl, nullptr, nullptr, nullptr, kb, D_DIM, D_DIM);
    lora_a_k<<<M_ROWS / 8, 256>>>(y, wvA, ta, D_DIM);
    split_k<<<(D_DIM * D_DIM / 4) / 256, 256>>>(wvW, wh, wl, D_DIM * D_DIM / 4);
    gemm_mma<1,0,0,1><<<dim3(8, 32), 256, SMEM_GEMM>>>(ah, al, wh, wl, ta, wvB, nullptr, vb, D_DIM, D_DIM);
    attn_mma<<<dim3(32, H_NUM, B_DIM), 128, SMEM_ATTN>>>(qb, kb, vb, relb, o);
    lora_a_k<<<M_ROWS / 8, 256>>>(o, fcA, ta, D_DIM);
    split_k<<<nDD / 256, 256>>>(o, ah, al, nDD);
    split_k<<<(D_DIM * D_DIM / 4) / 256, 256>>>(fcW, wh, wl, D_DIM * D_DIM / 4);
    gemm_mma<1,1,0,0><<<dim3(8, 32), 256, SMEM_GEMM>>>(ah, al, wh, wl, ta, fcB, x, x1, D_DIM, D_DIM);
    // 3) GEGLU FFN branch
    rmsnorm_k<<<M_ROWS, 256>>>(x1, n3w, y);
    lora_a_k<<<M_ROWS / 8, 256>>>(y, w1A, ta, D_DIM);
    split_k<<<nDD / 256, 256>>>(y, ah, al, nDD);
    split_k<<<(4 * D_DIM * D_DIM / 4) / 256, 256>>>(w1W, wh, wl, 4 * D_DIM * D_DIM / 4);
    gemm_mma<1,0,1,0><<<dim3(32, 32), 256, SMEM_GEMM>>>(ah, al, wh, wl, ta, w1B, nullptr, hh, 4 * D_DIM, D_DIM);
    geglu_k<<<(M_ROWS * 512) / 256, 256>>>(hh, gl);
    lora_a_k<<<M_ROWS / 8, 256>>>(gl, w2A, ta, 2 * D_DIM);
    split_k<<<(M_ROWS * 2 * D_DIM / 4) / 256, 256>>>(gl, ah, al, M_ROWS * 2 * D_DIM / 4);
    split_k<<<(2 * D_DIM * D_DIM / 4) / 256, 256>>>(w2W, wh, wl, 2 * D_DIM * D_DIM / 4);
    gemm_mma<1,1,1,0><<<dim3(8, 32), 256, SMEM_GEMM>>>(ah, al, wh, wl, ta, w2B, x1, out, D_DIM, 2 * D_DIM);
}

// round 13
// speedup vs baseline: 4.9708x; 1.1311x over previous
#include <cuda_runtime.h>
#include <cuda_bf16.h>
#include <math.h>
#include <stdint.h>

#define T_DIM 2048
#define D_DIM 1024
#define B_DIM 2
#define H_NUM 16
#define M_ROWS 4096   // B*T

// ---------------- scratch (device globals; no allocation) ----------------
__device__ float g_o  [(size_t)M_ROWS * D_DIM];   // bf16 o (reinterpreted, half used)
__device__ float g_q  [(size_t)M_ROWS * D_DIM];   // bf16 q
__device__ float g_kk [(size_t)M_ROWS * D_DIM];   // bf16 k
__device__ float g_v  [(size_t)M_ROWS * D_DIM];   // bf16 v
__device__ float g_x1 [(size_t)M_ROWS * D_DIM];
__device__ float g_h  [(size_t)M_ROWS * 4 * D_DIM];
__device__ float g_ta [(size_t)M_ROWS * 8];
__device__ float g_tb [(size_t)M_ROWS * 8];
__device__ __nv_bfloat16 g_ah[(size_t)M_ROWS * 2 * D_DIM];
__device__ __nv_bfloat16 g_al[(size_t)M_ROWS * 2 * D_DIM];
__device__ __nv_bfloat16 g_wh[(size_t)4 * D_DIM * D_DIM];
__device__ __nv_bfloat16 g_wl[(size_t)4 * D_DIM * D_DIM];

// ---------------- PTX helpers (sm_80-era features only) ----------------
__device__ __forceinline__ uint32_t smem_u32(const void* p) {
    uint32_t a;
    asm("{ .reg .u64 t; cvta.to.shared.u64 t, %1; cvt.u32.u64 %0, t; }" : "=r"(a) : "l"(p));
    return a;
}
#define CP_ASYNC16(dst, src) \
    asm volatile("cp.async.cg.shared.global [%0], [%1], 16;" :: "r"(dst), "l"(src))
#define CP_COMMIT()   asm volatile("cp.async.commit_group;" ::: "memory")
#define CP_WAIT(n)    asm volatile("cp.async.wait_group %0;" :: "n"(n) : "memory")
#define LDMATRIX_X4(r0, r1, r2, r3, addr) \
    asm volatile("ldmatrix.sync.aligned.m8n8.x4.shared.b16 {%0,%1,%2,%3}, [%4];" \
        : "=r"(r0), "=r"(r1), "=r"(r2), "=r"(r3) : "r"(addr))
#define LDMATRIX_X4_T(r0, r1, r2, r3, addr) \
    asm volatile("ldmatrix.sync.aligned.m8n8.x4.trans.shared.b16 {%0,%1,%2,%3}, [%4];" \
        : "=r"(r0), "=r"(r1), "=r"(r2), "=r"(r3) : "r"(addr))

__device__ __forceinline__ void mma_bf16(float* d, const uint32_t* a,
                                         uint32_t b0, uint32_t b1) {
    asm volatile("mma.sync.aligned.m16n8k16.row.col.f32.bf16.bf16.f32 "
        "{%0,%1,%2,%3}, {%4,%5,%6,%7}, {%8,%9}, {%0,%1,%2,%3};"
        : "+f"(d[0]), "+f"(d[1]), "+f"(d[2]), "+f"(d[3])
        : "r"(a[0]), "r"(a[1]), "r"(a[2]), "r"(a[3]), "r"(b0), "r"(b1));
}
__device__ __forceinline__ uint32_t swz128(uint32_t off) {
    return off ^ ((off >> 3) & 0x70);
}
__device__ __forceinline__ uint32_t packbf(float lo, float hi) {
    uint32_t r;
    asm("cvt.rn.bf16x2.f32 %0, %1, %2;" : "=r"(r) : "f"(hi), "f"(lo));
    return r;
}
__device__ __forceinline__ float bf2f(uint32_t u16) {
    return __uint_as_float(u16 << 16);
}
// split one fp32 into (hi, lo) bf16 bit patterns
__device__ __forceinline__ void splt(float x, uint32_t& h, uint32_t& l) {
    __nv_bfloat16 hb = __float2bfloat16_rn(x);
    float r = x - __bfloat162float(hb);
    __nv_bfloat16 lb = __float2bfloat16_rn(r);
    h = (uint32_t)__bfloat16_as_ushort(hb);
    l = (uint32_t)__bfloat16_as_ushort(lb);
}

// ---------------- fp32 -> (hi[, lo]) bf16 split ----------------
template<int HIONLY>
__global__ void split_k(const float* __restrict__ X, __nv_bfloat16* __restrict__ Hi,
                        __nv_bfloat16* __restrict__ Lo, int n4) {
    int i = blockIdx.x * 256 + threadIdx.x;
    if (i >= n4) return;
    float4 x = ((const float4*)X)[i];
    float xs[4] = {x.x, x.y, x.z, x.w};
    uint32_t hu[4], lu[4];
    #pragma unroll
    for (int j = 0; j < 4; j++) splt(xs[j], hu[j], lu[j]);
    ((uint2*)Hi)[i] = make_uint2(hu[0] | (hu[1] << 16), hu[2] | (hu[3] << 16));
    if (!HIONLY)
        ((uint2*)Lo)[i] = make_uint2(lu[0] | (lu[1] << 16), lu[2] | (lu[3] << 16));
}

// ---------------- fused RMSNorm + split + LoRA-A (NL matrices) ----------------
template<int NL>
__global__ __launch_bounds__(256) void rmsnorm_lora_k(
    const float* __restrict__ X, const float* __restrict__ W,
    const float* __restrict__ A0, const float* __restrict__ A1,
    __nv_bfloat16* __restrict__ Hi, __nv_bfloat16* __restrict__ Lo,
    float* __restrict__ T0, float* __restrict__ T1) {
    int row = blockIdx.x, tid = threadIdx.x, lane = tid & 31, wid = tid >> 5;
    const float4* x4 = (const float4*)(X + (size_t)row * D_DIM);
    float4 v = x4[tid];
    float ss = v.x*v.x + v.y*v.y + v.z*v.z + v.w*v.w;
    #pragma unroll
    for (int off = 16; off; off >>= 1) ss += __shfl_xor_sync(0xffffffffu, ss, off);
    __shared__ float sred[8];
    __shared__ float spart[8][16];
    if (lane == 0) sred[wid] = ss;
    __syncthreads();
    float tot = 0.f;
    #pragma unroll
    for (int i = 0; i < 8; i++) tot += sred[i];
    float inv = rsqrtf(tot * (1.0f / D_DIM) + 1e-6f);
    float4 w = ((const float4*)W)[tid];
    float y0 = v.x * inv * w.x, y1 = v.y * inv * w.y;
    float y2 = v.z * inv * w.z, y3 = v.w * inv * w.w;
    // split write
    uint32_t h[4], l[4];
    splt(y0, h[0], l[0]); splt(y1, h[1], l[1]);
    splt(y2, h[2], l[2]); splt(y3, h[3], l[3]);
    ((uint2*)(Hi + (size_t)row * D_DIM))[tid] = make_uint2(h[0]|(h[1]<<16), h[2]|(h[3]<<16));
    ((uint2*)(Lo + (size_t)row * D_DIM))[tid] = make_uint2(l[0]|(l[1]<<16), l[2]|(l[3]<<16));
    // LoRA-A partials
    float acc[8 * NL];
    #pragma unroll
    for (int r = 0; r < 8 * NL; r++) acc[r] = 0.f;
    #pragma unroll
    for (int r = 0; r < 8; r++) {
        float4 a = ((const float4*)A0)[r * 256 + tid];
        acc[r] = y0*a.x + y1*a.y + y2*a.z + y3*a.w;
    }
    if (NL == 2) {
        #pragma unroll
        for (int r = 0; r < 8; r++) {
            float4 a = ((const float4*)A1)[r * 256 + tid];
            acc[8 + r] = y0*a.x + y1*a.y + y2*a.z + y3*a.w;
        }
    }
    #pragma unroll
    for (int r = 0; r < 8 * NL; r++) {
        float a = acc[r];
        #pragma unroll
        for (int off = 16; off; off >>= 1) a += __shfl_xor_sync(0xffffffffu, a, off);
        if (lane == 0) spart[wid][r] = a;
    }
    __syncthreads();
    if (tid < 8 * NL) {
        float s = 0.f;
        #pragma unroll
        for (int w8 = 0; w8 < 8; w8++) s += spart[w8][tid];
        if (tid < 8) T0[(size_t)row * 8 + tid] = s;
        else         T1[(size_t)row * 8 + (tid - 8)] = s;
    }
}

// ---------------- LoRA-A over bf16 input (for fc on attention output) ----------------
__global__ void lora_a_bf16_k(const __nv_bfloat16* __restrict__ Y,
                              const float* __restrict__ A, float* __restrict__ Tout) {
    int row  = blockIdx.x * 8 + (threadIdx.x >> 5);
    int lane = threadIdx.x & 31;
    const __nv_bfloat16* y = Y + (size_t)row * D_DIM;
    float acc[8] = {0,0,0,0,0,0,0,0};
    #pragma unroll
    for (int it = 0; it < 4; it++) {
        int k = it * 256 + lane * 8;
        uint4 yu = *(const uint4*)(y + k);
        float yv[8];
        yv[0] = bf2f(yu.x & 0xffff); yv[1] = bf2f(yu.x >> 16);
        yv[2] = bf2f(yu.y & 0xffff); yv[3] = bf2f(yu.y >> 16);
        yv[4] = bf2f(yu.z & 0xffff); yv[5] = bf2f(yu.z >> 16);
        yv[6] = bf2f(yu.w & 0xffff); yv[7] = bf2f(yu.w >> 16);
        #pragma unroll
        for (int r = 0; r < 8; r++) {
            float4 a0 = *(const float4*)(A + (size_t)r * D_DIM + k);
            float4 a1 = *(const float4*)(A + (size_t)r * D_DIM + k + 4);
            acc[r] += yv[0]*a0.x + yv[1]*a0.y + yv[2]*a0.z + yv[3]*a0.w
                    + yv[4]*a1.x + yv[5]*a1.y + yv[6]*a1.z + yv[7]*a1.w;
        }
    }
    #pragma unroll
    for (int r = 0; r < 8; r++) {
        float a = acc[r];
        #pragma unroll
        for (int off = 16; off; off >>= 1) a += __shfl_xor_sync(0xffffffffu, a, off);
        if (lane == 0) Tout[(size_t)row * 8 + r] = a;
    }
}

// ---------------- fused GEGLU + split + LoRA-A(w2A, K=2048) ----------------
__global__ __launch_bounds__(256) void geglu_lora_k(
    const float* __restrict__ Hh, const float* __restrict__ A,
    __nv_bfloat16* __restrict__ Hi, __nv_bfloat16* __restrict__ Lo,
    float* __restrict__ Tout) {
    int m = blockIdx.x, tid = threadIdx.x, lane = tid & 31, wid = tid >> 5;
    const float* hrow = Hh + (size_t)m * 4096;
    float acc[8] = {0,0,0,0,0,0,0,0};
    #pragma unroll
    for (int j = 0; j < 2; j++) {
        int c = tid * 8 + j * 4;
        float4 a = *(const float4*)(hrow + c);
        float4 g = *(const float4*)(hrow + 2048 + c);
        float av[4] = {a.x, a.y, a.z, a.w};
        float gv[4] = {g.x, g.y, g.z, g.w};
        float rr[4];
        #pragma unroll
        for (int i = 0; i < 4; i++) {
            float xg = gv[i];
            float t = 0.7978845608028654f * (xg + 0.044715f * xg * xg * xg);
            rr[i] = av[i] * 0.5f * xg * (1.0f + tanhf(t));
        }
        uint32_t h[4], l[4];
        #pragma unroll
        for (int i = 0; i < 4; i++) splt(rr[i], h[i], l[i]);
        *(uint2*)(Hi + (size_t)m * 2048 + c) = make_uint2(h[0]|(h[1]<<16), h[2]|(h[3]<<16));
        *(uint2*)(Lo + (size_t)m * 2048 + c) = make_uint2(l[0]|(l[1]<<16), l[2]|(l[3]<<16));
        #pragma unroll
        for (int r = 0; r < 8; r++) {
            float4 av4 = *(const float4*)(A + (size_t)r * 2048 + c);
            acc[r] += rr[0]*av4.x + rr[1]*av4.y + rr[2]*av4.z + rr[3]*av4.w;
        }
    }
    __shared__ float spart[8][8];
    #pragma unroll
    for (int r = 0; r < 8; r++) {
        float a = acc[r];
        #pragma unroll
        for (int off = 16; off; off >>= 1) a += __shfl_xor_sync(0xffffffffu, a, off);
        if (lane == 0) spart[wid][r] = a;
    }
    __syncthreads();
    if (tid < 8) {
        float s = 0.f;
        #pragma unroll
        for (int w8 = 0; w8 < 8; w8++) s += spart[w8][tid];
        Tout[(size_t)m * 8 + tid] = s;
    }
}

// ---------------- HMMA GEMM (NT): C = A*W^T ----------------
#define SM_STAGE  65536
#define SMEM_GEMM (2 * SM_STAGE)

template<int LORA, int RES, int SPLIT, int OUTBF16>
__global__ __launch_bounds__(256) void gemm_mma(
    const __nv_bfloat16* __restrict__ Ah, const __nv_bfloat16* __restrict__ Al,
    const __nv_bfloat16* __restrict__ Wh, const __nv_bfloat16* __restrict__ Wl,
    const float* __restrict__ TL, const float* __restrict__ BLg,
    const float* __restrict__ R, void* __restrict__ Cv, int N, int K) {
    extern __shared__ char sraw[];
    const uint32_t sb = smem_u32(sraw);
    const int tid = threadIdx.x, wid = tid >> 5, lane = tid & 31;
    const int wm = wid >> 2, wn = wid & 3;
    const int bm = blockIdx.y * 128, bn = blockIdx.x * 128;

    const __nv_bfloat16* srcs[4] = {
        Ah + (size_t)bm * K, Al + (size_t)bm * K,
        Wh + (size_t)bn * K, Wl + (size_t)bn * K };

    const int fr = tid >> 3, fc = (tid & 7) * 8;

    auto fill = [&](int stage, int k0) {
        const uint32_t sbase = sb + stage * SM_STAGE;
        #pragma unroll
        for (int t = 0; t < 4; t++) {
            if (!SPLIT && (t == 1 || t == 3)) continue;
            const __nv_bfloat16* src = srcs[t] + k0 + fc;
            uint32_t dstb = sbase + t * 16384;
            #pragma unroll
            for (int i = 0; i < 4; i++) {
                int r = fr + i * 32;
                uint32_t off = swz128(r * 128 + fc * 2);
                CP_ASYNC16(dstb + off, src + (size_t)r * K);
            }
        }
        CP_COMMIT();
    };

    float acc[4][4][4] = {};
    const int nch = K / 64;

    fill(0, 0);
    for (int ch = 0; ch < nch; ch++) {
        if (ch + 1 < nch) { fill((ch + 1) & 1, (ch + 1) * 64); CP_WAIT(1); }
        else CP_WAIT(0);
        __syncthreads();
        const uint32_t sbase = sb + (ch & 1) * SM_STAGE;
        #pragma unroll
        for (int ks = 0; ks < 4; ks++) {
            const int kb = ks * 32 + (lane >> 4) * 16;
            uint32_t ah[4][4], al[4][4], wh[2][4], wl[2][4];
            #pragma unroll
            for (int mt = 0; mt < 4; mt++) {
                int row = wm * 64 + mt * 16 + (lane & 15);
                uint32_t off = swz128(row * 128 + kb);
                LDMATRIX_X4(ah[mt][0], ah[mt][1], ah[mt][2], ah[mt][3], sbase + off);
                if (SPLIT)
                    LDMATRIX_X4(al[mt][0], al[mt][1], al[mt][2], al[mt][3], sbase + 16384 + off);
            }
            #pragma unroll
            for (int ng = 0; ng < 2; ng++) {
                int row = wn * 32 + ng * 16 + (lane & 15);
                uint32_t off = swz128(row * 128 + kb);
                LDMATRIX_X4(wh[ng][0], wh[ng][1], wh[ng][2], wh[ng][3], sbase + 32768 + off);
                if (SPLIT)
                    LDMATRIX_X4(wl[ng][0], wl[ng][1], wl[ng][2], wl[ng][3], sbase + 49152 + off);
            }
            #pragma unroll
            for (int mt = 0; mt < 4; mt++) {
                #pragma unroll
                for (int ng = 0; ng < 2; ng++) {
                    mma_bf16(acc[mt][2*ng+0], ah[mt], wh[ng][0], wh[ng][2]);
                    mma_bf16(acc[mt][2*ng+1], ah[mt], wh[ng][1], wh[ng][3]);
                    if (SPLIT) {
                        mma_bf16(acc[mt][2*ng+0], ah[mt], wl[ng][0], wl[ng][2]);
                        mma_bf16(acc[mt][2*ng+1], ah[mt], wl[ng][1], wl[ng][3]);
                        mma_bf16(acc[mt][2*ng+0], al[mt], wh[ng][0], wh[ng][2]);
                        mma_bf16(acc[mt][2*ng+1], al[mt], wh[ng][1], wh[ng][3]);
                    }
                }
            }
        }
        __syncthreads();
    }

    float* C = (float*)Cv;
    __nv_bfloat16* Cb = (__nv_bfloat16*)Cv;
    #pragma unroll
    for (int mt = 0; mt < 4; mt++) {
        #pragma unroll
        for (int h2 = 0; h2 < 2; h2++) {
            int row = bm + wm * 64 + mt * 16 + (lane >> 2) + h2 * 8;
            float tl[8];
            if (LORA) {
                float4 t0 = *(const float4*)(TL + (size_t)row * 8);
                float4 t1 = *(const float4*)(TL + (size_t)row * 8 + 4);
                tl[0]=t0.x; tl[1]=t0.y; tl[2]=t0.z; tl[3]=t0.w;
                tl[4]=t1.x; tl[5]=t1.y; tl[6]=t1.z; tl[7]=t1.w;
            }
            #pragma unroll
            for (int nt = 0; nt < 4; nt++) {
                int col = bn + wn * 32 + nt * 8 + (lane & 3) * 2;
                float v0 = acc[mt][nt][h2 * 2 + 0];
                float v1 = acc[mt][nt][h2 * 2 + 1];
                if (LORA) {
                    const float* b0 = BLg + (size_t)col * 8;
                    float d0 = 0.f, d1 = 0.f;
                    #pragma unroll
                    for (int r = 0; r < 8; r++) {
                        d0 += tl[r] * b0[r];
                        d1 += tl[r] * b0[8 + r];
                    }
                    v0 += 0.125f * d0; v1 += 0.125f * d1;
                }
                size_t off = (size_t)row * N + col;
                if (RES) {
                    float2 rr = *(const float2*)(R + off);
                    v0 += rr.x; v1 += rr.y;
                }
                if (OUTBF16) {
                    *(uint32_t*)(Cb + off) = packbf(v0, v1);
                } else {
                    *(float2*)(C + off) = make_float2(v0, v1);
                }
            }
        }
    }
}

// ---------------- T5 relative bucket ----------------
__device__ __forceinline__ int rel_bucket(int rel) {
    int b = (rel > 0) ? 16 : 0;
    int ar = rel < 0 ? -rel : rel;
    int t;
    if      (ar <  8) t = ar;
    else if (ar < 12) t = 8;
    else if (ar < 16) t = 9;
    else if (ar < 23) t = 10;
    else if (ar < 32) t = 11;
    else if (ar < 46) t = 12;
    else if (ar < 64) t = 13;
    else if (ar < 91) t = 14;
    else              t = 15;
    return b + t;
}

__global__ void posbias_k(const float* __restrict__ RB, float* __restrict__ out) {
    int idx = blockIdx.x * 256 + threadIdx.x;
    int i = idx >> 11, j = idx & 2047;
    int bu = rel_bucket(j - i);
    const float* rb = RB + bu * H_NUM;
    #pragma unroll
    for (int h = 0; h < H_NUM; h++)
        out[(size_t)h * T_DIM * T_DIM + idx] = __ldg(rb + h);
}

// ---------------- HMMA flash attention (bf16 QKV, fp32 accum, bf16 out) ----------------
#define SMEM_ATTN 57344

__global__ __launch_bounds__(128) void attn_mma(
    const __nv_bfloat16* __restrict__ Qg, const __nv_bfloat16* __restrict__ Kg,
    const __nv_bfloat16* __restrict__ Vg, const float* __restrict__ relb,
    __nv_bfloat16* __restrict__ Ob) {
    extern __shared__ char sraw[];
    const uint32_t sb = smem_u32(sraw);
    float* LUT = (float*)(sraw + 40960);
    const int tid = threadIdx.x, wid = tid >> 5, lane = tid & 31;
    const int q0 = blockIdx.x * 64, h = blockIdx.y, b = blockIdx.z;

    for (int i = tid; i < 4095; i += 128)
        LUT[i] = __ldg(&relb[rel_bucket(i - 2047) * H_NUM + h]);

    const __nv_bfloat16* Qrow = Qg + ((size_t)(b * T_DIM + q0)) * D_DIM + h * 64;
    #pragma unroll
    for (int i = 0; i < 4; i++) {
        int w = tid + i * 128;
        int r = w >> 3, c8 = (w & 7) * 8;
        CP_ASYNC16(sb + swz128(r * 128 + c8 * 2), Qrow + (size_t)r * D_DIM + c8);
    }
    auto fillkv = [&](int st, int kt) {
        const __nv_bfloat16* Kr = Kg + ((size_t)(b * T_DIM + kt * 64)) * D_DIM + h * 64;
        const __nv_bfloat16* Vr = Vg + ((size_t)(b * T_DIM + kt * 64)) * D_DIM + h * 64;
        uint32_t base = sb + 8192 + st * 16384;
        #pragma unroll
        for (int i = 0; i < 4; i++) {
            int w = tid + i * 128;
            int r = w >> 3, c8 = (w & 7) * 8;
            uint32_t off = swz128(r * 128 + c8 * 2);
            CP_ASYNC16(base + off, Kr + (size_t)r * D_DIM + c8);
            CP_ASYNC16(base + 8192 + off, Vr + (size_t)r * D_DIM + c8);
        }
    };
    fillkv(0, 0);
    CP_COMMIT();

    float oacc[8][4] = {};
    float m0 = -1e30f, m1 = -1e30f, l0 = 0.f, l1 = 0.f;
    const int qrow = q0 + wid * 16 + (lane >> 2);

    for (int jt = 0; jt < 32; jt++) {
        if (jt + 1 < 32) { fillkv((jt + 1) & 1, jt + 1); CP_COMMIT(); CP_WAIT(1); }
        else CP_WAIT(0);
        __syncthreads();
        const uint32_t Kb = sb + 8192 + (jt & 1) * 16384;
        const uint32_t Vb = Kb + 8192;

        float s[8][4] = {};
        #pragma unroll
        for (int kc = 0; kc < 4; kc++) {
            const int kb = kc * 32 + (lane >> 4) * 16;
            uint32_t qf[4];
            LDMATRIX_X4(qf[0], qf[1], qf[2], qf[3],
                        sb + swz128((wid * 16 + (lane & 15)) * 128 + kb));
            #pragma unroll
            for (int ng = 0; ng < 4; ng++) {
                uint32_t kf[4];
                LDMATRIX_X4(kf[0], kf[1], kf[2], kf[3],
                            Kb + swz128((ng * 16 + (lane & 15)) * 128 + kb));
                mma_bf16(s[2*ng+0], qf, kf[0], kf[2]);
                mma_bf16(s[2*ng+1], qf, kf[1], kf[3]);
            }
        }
        const int db0 = jt * 64 - qrow + 2047 + 2 * (lane & 3);
        float mx0 = -1e30f, mx1 = -1e30f;
        #pragma unroll
        for (int t = 0; t < 8; t++) {
            int ib = db0 + t * 8;
            s[t][0] = s[t][0] * 0.125f + LUT[ib];
            s[t][1] = s[t][1] * 0.125f + LUT[ib + 1];
            s[t][2] = s[t][2] * 0.125f + LUT[ib - 8];
            s[t][3] = s[t][3] * 0.125f + LUT[ib - 7];
            mx0 = fmaxf(mx0, fmaxf(s[t][0], s[t][1]));
            mx1 = fmaxf(mx1, fmaxf(s[t][2], s[t][3]));
        }
        mx0 = fmaxf(mx0, __shfl_xor_sync(0xffffffffu, mx0, 1));
        mx0 = fmaxf(mx0, __shfl_xor_sync(0xffffffffu, mx0, 2));
        mx1 = fmaxf(mx1, __shfl_xor_sync(0xffffffffu, mx1, 1));
        mx1 = fmaxf(mx1, __shfl_xor_sync(0xffffffffu, mx1, 2));
        float nm0 = fmaxf(m0, mx0), nm1 = fmaxf(m1, mx1);
        float c0 = __expf(m0 - nm0), c1 = __expf(m1 - nm1);
        m0 = nm0; m1 = nm1;
        float rs0 = 0.f, rs1 = 0.f;
        #pragma unroll
        for (int t = 0; t < 8; t++) {
            s[t][0] = __expf(s[t][0] - nm0); rs0 += s[t][0];
            s[t][1] = __expf(s[t][1] - nm0); rs0 += s[t][1];
            s[t][2] = __expf(s[t][2] - nm1); rs1 += s[t][2];
            s[t][3] = __expf(s[t][3] - nm1); rs1 += s[t][3];
        }
        rs0 += __shfl_xor_sync(0xffffffffu, rs0, 1);
        rs0 += __shfl_xor_sync(0xffffffffu, rs0, 2);
        rs1 += __shfl_xor_sync(0xffffffffu, rs1, 1);
        rs1 += __shfl_xor_sync(0xffffffffu, rs1, 2);
        l0 = l0 * c0 + rs0; l1 = l1 * c1 + rs1;
        #pragma unroll
        for (int t = 0; t < 8; t++) {
            oacc[t][0] *= c0; oacc[t][1] *= c0;
            oacc[t][2] *= c1; oacc[t][3] *= c1;
        }
        #pragma unroll
        for (int c = 0; c < 4; c++) {
            uint32_t af[4];
            af[0] = packbf(s[2*c+0][0], s[2*c+0][1]);
            af[1] = packbf(s[2*c+0][2], s[2*c+0][3]);
            af[2] = packbf(s[2*c+1][0], s[2*c+1][1]);
            af[3] = packbf(s[2*c+1][2], s[2*c+1][3]);
            #pragma unroll
            for (int j = 0; j < 4; j++) {
                uint32_t vf[4];
                int row = c * 16 + ((lane >> 4) * 8) + (lane & 7);
                int colb = j * 32 + ((lane >> 3) & 1) * 16;
                LDMATRIX_X4_T(vf[0], vf[1], vf[2], vf[3], Vb + swz128(row * 128 + colb));
                mma_bf16(oacc[2*j+0], af, vf[0], vf[2]);
                mma_bf16(oacc[2*j+1], af, vf[1], vf[3]);
            }
        }
        __syncthreads();
    }
    float inv0 = 1.0f / l0, inv1 = 1.0f / l1;
    size_t row0 = (size_t)(b * T_DIM + qrow) * D_DIM + h * 64;
    size_t row1 = row0 + 8 * D_DIM;
    #pragma unroll
    for (int t = 0; t < 8; t++) {
        int col = t * 8 + (lane & 3) * 2;
        *(uint32_t*)(Ob + row0 + col) = packbf(oacc[t][0] * inv0, oacc[t][1] * inv0);
        *(uint32_t*)(Ob + row1 + col) = packbf(oacc[t][2] * inv1, oacc[t][3] * inv1);
    }
}

// ---------------- host ----------------
extern "C" void kernel_launch(void* const* d_in, const int* in_sizes, int n_in,
                              void* d_out, int out_size) {
    (void)in_sizes; (void)n_in; (void)out_size;
    const float* x    = (const float*)d_in[0];
    const float* n1w  = (const float*)d_in[3];
    const float* n3w  = (const float*)d_in[4];
    const float* wqW  = (const float*)d_in[5];
    const float* wqA  = (const float*)d_in[6];
    const float* wqB  = (const float*)d_in[7];
    const float* wkW  = (const float*)d_in[8];
    const float* wvW  = (const float*)d_in[9];
    const float* wvA  = (const float*)d_in[10];
    const float* wvB  = (const float*)d_in[11];
    const float* fcW  = (const float*)d_in[12];
    const float* fcA  = (const float*)d_in[13];
    const float* fcB  = (const float*)d_in[14];
    const float* relb = (const float*)d_in[15];
    const float* w1W  = (const float*)d_in[16];
    const float* w1A  = (const float*)d_in[17];
    const float* w1B  = (const float*)d_in[18];
    const float* w2W  = (const float*)d_in[19];
    const float* w2A  = (const float*)d_in[20];
    const float* w2B  = (const float*)d_in[21];

    float* out = (float*)d_out;
    float* pb  = out + (size_t)M_ROWS * D_DIM;

    float *o, *q, *k, *v, *x1, *hh, *ta, *tb;
    __nv_bfloat16 *ah, *al, *wh, *wl;
    cudaGetSymbolAddress((void**)&o,  g_o);
    cudaGetSymbolAddress((void**)&q,  g_q);
    cudaGetSymbolAddress((void**)&k,  g_kk);
    cudaGetSymbolAddress((void**)&v,  g_v);
    cudaGetSymbolAddress((void**)&x1, g_x1);
    cudaGetSymbolAddress((void**)&hh, g_h);
    cudaGetSymbolAddress((void**)&ta, g_ta);
    cudaGetSymbolAddress((void**)&tb, g_tb);
    cudaGetSymbolAddress((void**)&ah, g_ah);
    cudaGetSymbolAddress((void**)&al, g_al);
    cudaGetSymbolAddress((void**)&wh, g_wh);
    cudaGetSymbolAddress((void**)&wl, g_wl);
    __nv_bfloat16* qb = (__nv_bfloat16*)q;
    __nv_bfloat16* kb = (__nv_bfloat16*)k;
    __nv_bfloat16* vb = (__nv_bfloat16*)v;
    __nv_bfloat16* ob = (__nv_bfloat16*)o;

    cudaFuncSetAttribute(gemm_mma<1,0,0,1>, cudaFuncAttributeMaxDynamicSharedMemorySize, SMEM_GEMM);
    cudaFuncSetAttribute(gemm_mma<0,0,0,1>, cudaFuncAttributeMaxDynamicSharedMemorySize, SMEM_GEMM);
    cudaFuncSetAttribute(gemm_mma<1,1,0,0>, cudaFuncAttributeMaxDynamicSharedMemorySize, SMEM_GEMM);
    cudaFuncSetAttribute(gemm_mma<1,0,1,0>, cudaFuncAttributeMaxDynamicSharedMemorySize, SMEM_GEMM);
    cudaFuncSetAttribute(gemm_mma<1,1,1,0>, cudaFuncAttributeMaxDynamicSharedMemorySize, SMEM_GEMM);
    cudaFuncSetAttribute(attn_mma, cudaFuncAttributeMaxDynamicSharedMemorySize, SMEM_ATTN);

    const int nW1 = D_DIM * D_DIM / 4;
    // 1) pos_bias output
    posbias_k<<<(T_DIM * T_DIM) / 256, 256>>>(relb, pb);
    // 2) attention branch: fused rmsnorm+split+lora (wqA, wvA)
    rmsnorm_lora_k<2><<<M_ROWS, 256>>>(x, n1w, wqA, wvA, ah, al, ta, tb);
    split_k<1><<<nW1 / 256, 256>>>(wqW, wh, nullptr, nW1);
    gemm_mma<1,0,0,1><<<dim3(8, 32), 256, SMEM_GEMM>>>(ah, al, wh, wl, ta, wqB, nullptr, qb, D_DIM, D_DIM);
    split_k<1><<<nW1 / 256, 256>>>(wkW, wh, nullptr, nW1);
    gemm_mma<0,0,0,1><<<dim3(8, 32), 256, SMEM_GEMM>>>(ah, al, wh, wl, nullptr, nullptr, nullptr, kb, D_DIM, D_DIM);
    split_k<1><<<nW1 / 256, 256>>>(wvW, wh, nullptr, nW1);
    gemm_mma<1,0,0,1><<<dim3(8, 32), 256, SMEM_GEMM>>>(ah, al, wh, wl, tb, wvB, nullptr, vb, D_DIM, D_DIM);
    attn_mma<<<dim3(32, H_NUM, B_DIM), 128, SMEM_ATTN>>>(qb, kb, vb, relb, ob);
    lora_a_bf16_k<<<M_ROWS / 8, 256>>>(ob, fcA, ta);
    split_k<1><<<nW1 / 256, 256>>>(fcW, wh, nullptr, nW1);
    gemm_mma<1,1,0,0><<<dim3(8, 32), 256, SMEM_GEMM>>>(ob, nullptr, wh, nullptr, ta, fcB, x, x1, D_DIM, D_DIM);
    // 3) GEGLU FFN branch
    rmsnorm_lora_k<1><<<M_ROWS, 256>>>(x1, n3w, w1A, nullptr, ah, al, ta, nullptr);
    split_k<0><<<(4 * nW1) / 256, 256>>>(w1W, wh, wl, 4 * nW1);
    gemm_mma<1,0,1,0><<<dim3(32, 32), 256, SMEM_GEMM>>>(ah, al, wh, wl, ta, w1B, nullptr, hh, 4 * D_DIM, D_DIM);
    geglu_lora_k<<<M_ROWS, 256>>>(hh, w2A, ah, al, ta);
    split_k<0><<<(2 * nW1) / 256, 256>>>(w2W, wh, wl, 2 * nW1);
    gemm_mma<1,1,1,0><<<dim3(8, 32), 256, SMEM_GEMM>>>(ah, al, wh, wl, ta, w2B, x1, out, D_DIM, 2 * D_DIM);
}